// round 5
// baseline (speedup 1.0000x reference)
#include <cuda_runtime.h>
#include <cuda_bf16.h>
#include <cstdint>

#define Bsz 4
#define Ssz 128
#define Esz 512
#define Hn 8
#define HDsz 64
#define FFsz 2048
#define Lnum 4
#define Msz (Bsz*Ssz)   /* 512 rows */

// ===================== scratch (static device memory) ======================
__device__ float g_h[Msz*Esz];
__device__ float g_qkv[4*Msz*Esz];
__device__ float g_kproj[1024*Esz];
__device__ float g_A1[Bsz*Hn*Ssz*Ssz];
__device__ float g_A2[Bsz*Hn*Ssz*Ssz];
__device__ float g_ap[Bsz*Hn*Ssz*11];
__device__ float g_attnsum[Msz*Esz];
__device__ float g_tmp[Msz*Esz];
__device__ float g_ff[Msz*FFsz];

// bf16 hi/lo split buffers
__device__ __align__(16) __nv_bfloat16 g_h_hi[Msz*Esz],  g_h_lo[Msz*Esz];
__device__ __align__(16) __nv_bfloat16 g_as_hi[Msz*Esz], g_as_lo[Msz*Esz];
__device__ __align__(16) __nv_bfloat16 g_ff_hi[Msz*FFsz],g_ff_lo[Msz*FFsz];
__device__ __align__(16) __nv_bfloat16 g_kn_hi[1000*Esz],g_kn_lo[1000*Esz];
__device__ __align__(16) __nv_bfloat16 g_Wq_hi[Lnum*Esz*Esz],  g_Wq_lo[Lnum*Esz*Esz];
__device__ __align__(16) __nv_bfloat16 g_Wk_hi[Lnum*Esz*Esz],  g_Wk_lo[Lnum*Esz*Esz];
__device__ __align__(16) __nv_bfloat16 g_Wvs_hi[Lnum*Esz*Esz], g_Wvs_lo[Lnum*Esz*Esz];
__device__ __align__(16) __nv_bfloat16 g_Wvo_hi[Lnum*Esz*Esz], g_Wvo_lo[Lnum*Esz*Esz];
__device__ __align__(16) __nv_bfloat16 g_Wo_hi[Lnum*Esz*Esz],  g_Wo_lo[Lnum*Esz*Esz];
__device__ __align__(16) __nv_bfloat16 g_Wkn_hi[Lnum*Esz*Esz], g_Wkn_lo[Lnum*Esz*Esz];
__device__ __align__(16) __nv_bfloat16 g_w1_hi[Lnum*FFsz*Esz], g_w1_lo[Lnum*FFsz*Esz];
__device__ __align__(16) __nv_bfloat16 g_w2_hi[Lnum*Esz*FFsz], g_w2_lo[Lnum*Esz*FFsz];

// ===================== fp32 -> bf16 hi/lo split =============================
__device__ __forceinline__ void split1(float x, unsigned short& h, unsigned short& l)
{
    __nv_bfloat16 hb = __float2bfloat16(x);
    h = __bfloat16_as_ushort(hb);
    l = __bfloat16_as_ushort(__float2bfloat16(x - __bfloat162float(hb)));
}

__global__ void cvt_kernel(const float* __restrict__ src, float* __restrict__ dst,
                           __nv_bfloat16* __restrict__ hi, __nv_bfloat16* __restrict__ lo,
                           int n4)
{
    int i = blockIdx.x * 256 + threadIdx.x;
    if (i >= n4) return;
    float4 v = ((const float4*)src)[i];
    if (dst) ((float4*)dst)[i] = v;
    ushort4 h, l;
    split1(v.x, h.x, l.x); split1(v.y, h.y, l.y);
    split1(v.z, h.z, l.z); split1(v.w, h.w, l.w);
    ((ushort4*)hi)[i] = h;
    ((ushort4*)lo)[i] = l;
}

// ===================== mma.sync helpers =====================================
__device__ __forceinline__ void ldsm_x4(uint32_t& r0, uint32_t& r1,
                                        uint32_t& r2, uint32_t& r3, uint32_t addr)
{
    asm volatile("ldmatrix.sync.aligned.m8n8.x4.shared.b16 {%0,%1,%2,%3}, [%4];"
                 : "=r"(r0), "=r"(r1), "=r"(r2), "=r"(r3) : "r"(addr));
}
__device__ __forceinline__ void mma_bf16(float* c, const uint32_t* a, const uint32_t* b)
{
    asm volatile("mma.sync.aligned.m16n8k16.row.col.f32.bf16.bf16.f32 "
                 "{%0,%1,%2,%3},{%4,%5,%6,%7},{%8,%9},{%0,%1,%2,%3};"
                 : "+f"(c[0]), "+f"(c[1]), "+f"(c[2]), "+f"(c[3])
                 : "r"(a[0]), "r"(a[1]), "r"(a[2]), "r"(a[3]), "r"(b[0]), "r"(b[1]));
}
__device__ __forceinline__ uint32_t smem_u32(const void* p) {
    uint32_t a;
    asm("{ .reg .u64 t; cvta.to.shared.u64 t, %1; cvt.u32.u64 %0, t; }" : "=r"(a) : "l"(p));
    return a;
}
__device__ __forceinline__ void cp16(uint32_t dst, const void* src) {
    asm volatile("cp.async.cg.shared.global [%0], [%1], 16;" :: "r"(dst), "l"(src));
}
#define CP_COMMIT() asm volatile("cp.async.commit_group;" ::: "memory")

// ===================== tensor-core bf16x3 GEMM ==============================
// C[M,N] = A[M,K] @ W[N,K]^T. 128x128 CTA tile, K chunks of 64, cp.async
// double buffer. 8 warps (2m x 4n), warp tile 64x32.
#define BK 64
#define LDS 72                 /* padded elems per smem row */
#define PART (128*LDS*2)       /* bytes per matrix-part tile = 18432 */
#define STAGE (4*PART)         /* A_hi A_lo B_hi B_lo = 73728 */
#define GEMM_SMEM (2*STAGE)    /* 147456 */

extern __shared__ char dynsmem[];

// stage one 128x64 bf16 tile (hi+lo) via cp.async, row clamp for OOB
__device__ __forceinline__ void stage_part(
    const __nv_bfloat16* __restrict__ hi, const __nv_bfloat16* __restrict__ lo,
    int row0, int rows_tot, int k0, int K, uint32_t s_hi, uint32_t s_lo, int tid)
{
    int r = tid >> 1, half = tid & 1;
    int gr = min(row0 + r, rows_tot - 1);
    const char* ph = (const char*)(hi + (size_t)gr * K + k0 + half * 32);
    const char* pl = (const char*)(lo + (size_t)gr * K + k0 + half * 32);
    uint32_t so = (uint32_t)r * (LDS * 2) + half * 64;
    #pragma unroll
    for (int u = 0; u < 4; u++) {
        cp16(s_hi + so + u * 16, ph + u * 16);
        cp16(s_lo + so + u * 16, pl + u * 16);
    }
}

__device__ __forceinline__ void gemm_mma_body(
    const __nv_bfloat16* __restrict__ Ahi, const __nv_bfloat16* __restrict__ Alo,
    const __nv_bfloat16* __restrict__ Whi, const __nv_bfloat16* __restrict__ Wlo,
    const float* __restrict__ bias, float* __restrict__ C,
    __nv_bfloat16* __restrict__ Chi, __nv_bfloat16* __restrict__ Clo,
    int M, int N, int K, int act)
{
    uint32_t sb = smem_u32(dynsmem);
    int tid = threadIdx.x;                  // 256
    int lane = tid & 31, wid = tid >> 5;
    int wm = wid >> 2, wn = wid & 3;        // 2 x 4 warps
    int bm = blockIdx.y * 128, bn = blockIdx.x * 128;
    int nch = K / BK;

    float acc[4][4][4] = {};

    // prologue: stage chunk 0 into buf 0
    stage_part(Ahi, Alo, bm, M, 0, K, sb + 0 * PART, sb + 1 * PART, tid);
    stage_part(Whi, Wlo, bn, N, 0, K, sb + 2 * PART, sb + 3 * PART, tid);
    CP_COMMIT();

    for (int c = 0; c < nch; c++) {
        uint32_t base = sb + (uint32_t)(c & 1) * STAGE;
        if (c + 1 < nch) {
            uint32_t nb = sb + (uint32_t)((c + 1) & 1) * STAGE;
            stage_part(Ahi, Alo, bm, M, (c + 1) * BK, K, nb + 0 * PART, nb + 1 * PART, tid);
            stage_part(Whi, Wlo, bn, N, (c + 1) * BK, K, nb + 2 * PART, nb + 3 * PART, tid);
            CP_COMMIT();
            asm volatile("cp.async.wait_group 1;" ::: "memory");
        } else {
            asm volatile("cp.async.wait_group 0;" ::: "memory");
        }
        __syncthreads();

        // A fragment byte offset for this lane (row-major, pad LDS)
        uint32_t a_off = ((uint32_t)(wm * 64 + (lane & 15)) * LDS + ((lane & 16) >> 1)) * 2;
        // B fragment byte offset (rows = n)
        uint32_t b_off = ((uint32_t)(wn * 32 + (lane & 7) + ((lane & 16) >> 1)) * LDS
                          + (lane & 8)) * 2;
        #pragma unroll
        for (int ks = 0; ks < 4; ks++) {
            uint32_t a_hi[4][4], a_lo[4][4], b_hi[4][2], b_lo[4][2];
            #pragma unroll
            for (int tm = 0; tm < 4; tm++) {
                uint32_t ad = base + a_off + ((uint32_t)tm * 16 * LDS + ks * 16) * 2;
                ldsm_x4(a_hi[tm][0], a_hi[tm][1], a_hi[tm][2], a_hi[tm][3], ad);
                ldsm_x4(a_lo[tm][0], a_lo[tm][1], a_lo[tm][2], a_lo[tm][3], ad + PART);
            }
            #pragma unroll
            for (int tp = 0; tp < 2; tp++) {
                uint32_t bd = base + 2 * PART + b_off
                            + ((uint32_t)tp * 16 * LDS + ks * 16) * 2;
                ldsm_x4(b_hi[2*tp][0], b_hi[2*tp][1], b_hi[2*tp+1][0], b_hi[2*tp+1][1], bd);
                ldsm_x4(b_lo[2*tp][0], b_lo[2*tp][1], b_lo[2*tp+1][0], b_lo[2*tp+1][1],
                        bd + PART);
            }
            #pragma unroll
            for (int tm = 0; tm < 4; tm++)
                #pragma unroll
                for (int tn = 0; tn < 4; tn++) {
                    mma_bf16(acc[tm][tn], a_hi[tm], b_hi[tn]);
                    mma_bf16(acc[tm][tn], a_hi[tm], b_lo[tn]);
                    mma_bf16(acc[tm][tn], a_lo[tm], b_hi[tn]);
                }
        }
        __syncthreads();
    }

    // epilogue
    int mrow = bm + wm * 64 + (lane >> 2);
    int ncol = bn + wn * 32 + (lane & 3) * 2;
    #pragma unroll
    for (int tm = 0; tm < 4; tm++) {
        #pragma unroll
        for (int half = 0; half < 2; half++) {
            int m = mrow + tm * 16 + half * 8;
            if (m >= M) continue;
            size_t rb = (size_t)m * N;
            #pragma unroll
            for (int tn = 0; tn < 4; tn++) {
                int n = ncol + tn * 8;
                float v0 = acc[tm][tn][half * 2 + 0];
                float v1 = acc[tm][tn][half * 2 + 1];
                if (bias) { v0 += bias[n]; v1 += bias[n + 1]; }
                if (act) { v0 = fmaxf(v0, 0.f); v1 = fmaxf(v1, 0.f); }
                *(float2*)(C + rb + n) = make_float2(v0, v1);
                if (Chi) {
                    unsigned short h0, l0, h1, l1;
                    split1(v0, h0, l0); split1(v1, h1, l1);
                    *(uint32_t*)((__nv_bfloat16*)Chi + rb + n) =
                        (uint32_t)h0 | ((uint32_t)h1 << 16);
                    *(uint32_t*)((__nv_bfloat16*)Clo + rb + n) =
                        (uint32_t)l0 | ((uint32_t)l1 << 16);
                }
            }
        }
    }
}

__global__ void __launch_bounds__(256, 1) gemm_tc(
    const __nv_bfloat16* Ahi, const __nv_bfloat16* Alo,
    const __nv_bfloat16* Whi, const __nv_bfloat16* Wlo,
    const float* bias, float* C, __nv_bfloat16* Chi, __nv_bfloat16* Clo,
    int M, int N, int K, int act)
{
    gemm_mma_body(Ahi, Alo, Whi, Wlo, bias, C, Chi, Clo, M, N, K, act);
}

__global__ void __launch_bounds__(256, 1) gemm_tc4(
    const __nv_bfloat16* Ahi, const __nv_bfloat16* Alo,
    const __nv_bfloat16* W0h, const __nv_bfloat16* W0l,
    const __nv_bfloat16* W1h, const __nv_bfloat16* W1l,
    const __nv_bfloat16* W2h, const __nv_bfloat16* W2l,
    const __nv_bfloat16* W3h, const __nv_bfloat16* W3l,
    float* C, int M, int N, int K)
{
    int z = blockIdx.z;
    const __nv_bfloat16* wh = (z == 0) ? W0h : (z == 1) ? W1h : (z == 2) ? W2h : W3h;
    const __nv_bfloat16* wl = (z == 0) ? W0l : (z == 1) ? W1l : (z == 2) ? W2l : W3l;
    gemm_mma_body(Ahi, Alo, wh, wl, nullptr, C + (size_t)z * M * N,
                  nullptr, nullptr, M, N, K, 0);
}

// ======== fused scores + softmax + mask-split + pos-histogram ==============
__global__ void scores_kernel(const float* __restrict__ q, const float* __restrict__ k,
                              const float* __restrict__ kproj,
                              const int* __restrict__ know_adj,
                              const int* __restrict__ pos_mask,
                              const int* __restrict__ adj,
                              const int* __restrict__ smk, const int* __restrict__ omk,
                              const float* __restrict__ pe_k,
                              float* __restrict__ A1, float* __restrict__ A2,
                              float* __restrict__ attn_pos)
{
    int i = blockIdx.x, b = blockIdx.y;
    int tid = threadIdx.x;                  // 0..255
    __shared__ float q_sh[512];
    __shared__ float sc[8 * 128];
    __shared__ float qr[8 * 11];
    __shared__ int   ka_sh[128];
    __shared__ int   p_sh[128];

    q_sh[tid]       = q[(size_t)(b * Ssz + i) * Esz + tid];
    q_sh[tid + 256] = q[(size_t)(b * Ssz + i) * Esz + tid + 256];
    if (tid < 128) {
        int ka = know_adj[(size_t)(b * Ssz + i) * Ssz + tid];
        ka_sh[tid] = min(max(ka, 0), 999);
        int p = pos_mask[i * Ssz + tid];
        p_sh[tid] = min(max(p, 0), 10);
    }
    __syncthreads();

    {
        int j  = tid & 127;
        int hb = tid >> 7;
        const float4* krow = (const float4*)(k + (size_t)(b * Ssz + j) * Esz + hb * 256);
        const float4* kprow = (const float4*)(kproj + (size_t)ka_sh[j] * Esz + hb * 256);
        const float4* qv = (const float4*)(q_sh + hb * 256);
        #pragma unroll
        for (int hh = 0; hh < 4; hh++) {
            float a = 0.f;
            #pragma unroll
            for (int u = 0; u < 16; u++) {
                int v = hh * 16 + u;
                float4 kv = krow[v];
                float4 kp = kprow[v];
                float4 qq = qv[v];
                a += qq.x * (kv.x + kp.x) + qq.y * (kv.y + kp.y)
                   + qq.z * (kv.z + kp.z) + qq.w * (kv.w + kp.w);
            }
            sc[(4 * hb + hh) * 128 + j] = a;
        }
    }
    if (tid < 88) {
        int h = tid / 11, p = tid % 11;
        float s = 0.f;
        const float4* pk = (const float4*)(pe_k + p * HDsz);
        const float4* qv = (const float4*)(q_sh + h * 64);
        #pragma unroll
        for (int v = 0; v < 16; v++) {
            float4 e = pk[v], qq = qv[v];
            s += qq.x * e.x + qq.y * e.y + qq.z * e.z + qq.w * e.w;
        }
        qr[h * 11 + p] = s;
    }
    __syncthreads();

    {
        int w = tid >> 5, l = tid & 31;
        float s[4];
        float m = -3.4e38f;
        #pragma unroll
        for (int t = 0; t < 4; t++) {
            int j = l + 32 * t;
            float ss = (sc[w * 128 + j] + qr[w * 11 + p_sh[j]]) * 0.125f;
            if (adj[(size_t)(b * Ssz + i) * Ssz + j] == 0) ss -= 1e30f;
            s[t] = ss;
            m = fmaxf(m, ss);
        }
        #pragma unroll
        for (int o = 16; o; o >>= 1) m = fmaxf(m, __shfl_xor_sync(0xffffffffu, m, o));
        float sum = 0.f;
        float e[4];
        #pragma unroll
        for (int t = 0; t < 4; t++) { e[t] = __expf(s[t] - m); sum += e[t]; }
        #pragma unroll
        for (int o = 16; o; o >>= 1) sum += __shfl_xor_sync(0xffffffffu, sum, o);
        float inv = 1.f / sum;
        size_t rbase = ((size_t)(b * Hn + w) * Ssz + i) * Ssz;
        #pragma unroll
        for (int t = 0; t < 4; t++) {
            int j = l + 32 * t;
            float attn = e[t] * inv;
            A1[rbase + j] = attn * (float)smk[(size_t)(b * Ssz + i) * Ssz + j];
            A2[rbase + j] = attn * (float)omk[(size_t)(b * Ssz + i) * Ssz + j];
            sc[w * 128 + j] = attn;
        }
    }
    __syncthreads();

    if (tid < 88) {
        int h = tid / 11, p = tid % 11;
        float s = 0.f;
        for (int j = 0; j < 128; j++)
            if (p_sh[j] == p) s += sc[h * 128 + j];
        attn_pos[((size_t)(b * Hn + h) * Ssz + i) * 11 + p] = s;
    }
}

// ================= attention value sum (+ bf16 split out) ==================
__global__ void attnsum_kernel(const float* __restrict__ vs, const float* __restrict__ vo,
                               const float* __restrict__ A1, const float* __restrict__ A2,
                               const float* __restrict__ attn_pos,
                               const float* __restrict__ pe_v,
                               float* __restrict__ outbuf,
                               __nv_bfloat16* __restrict__ ohi,
                               __nv_bfloat16* __restrict__ olo)
{
    int itile = blockIdx.x, hh = blockIdx.y, b = blockIdx.z;
    int tid = threadIdx.x;
    int grp = tid >> 6, d = tid & 63;
    __shared__ float vsh[128 * 65];

    for (int idx = tid; idx < 128 * 64; idx += 256) {
        int j = idx >> 6, dd = idx & 63;
        vsh[j * 65 + dd] = vs[(size_t)(b * Ssz + j) * Esz + hh * HDsz + dd];
    }
    __syncthreads();

    float acc[8];
    #pragma unroll
    for (int it = 0; it < 8; it++) {
        int i = itile * 32 + it * 4 + grp;
        const float* a1 = A1 + ((size_t)(b * Hn + hh) * Ssz + i) * Ssz;
        float s = 0.f;
        #pragma unroll 4
        for (int jj = 0; jj < 128; jj++) s += a1[jj] * vsh[jj * 65 + d];
        acc[it] = s;
    }
    __syncthreads();
    for (int idx = tid; idx < 128 * 64; idx += 256) {
        int j = idx >> 6, dd = idx & 63;
        vsh[j * 65 + dd] = vo[(size_t)(b * Ssz + j) * Esz + hh * HDsz + dd];
    }
    __syncthreads();
    #pragma unroll
    for (int it = 0; it < 8; it++) {
        int i = itile * 32 + it * 4 + grp;
        const float* a2 = A2 + ((size_t)(b * Hn + hh) * Ssz + i) * Ssz;
        float s = acc[it];
        #pragma unroll 4
        for (int jj = 0; jj < 128; jj++) s += a2[jj] * vsh[jj * 65 + d];
        const float* app = attn_pos + ((size_t)(b * Hn + hh) * Ssz + i) * 11;
        #pragma unroll
        for (int p = 0; p < 11; p++) s += app[p] * pe_v[p * HDsz + d];
        size_t oi = (size_t)(b * Ssz + i) * Esz + hh * HDsz + d;
        outbuf[oi] = s;
        unsigned short hv, lv;
        split1(s, hv, lv);
        ohi[oi] = __ushort_as_bfloat16(hv);
        olo[oi] = __ushort_as_bfloat16(lv);
    }
}

// ============== residual + layernorm (+ bf16 split out) ====================
__global__ void ln_kernel(const float* __restrict__ x, const float* __restrict__ dlt,
                          const float* __restrict__ g, const float* __restrict__ bt,
                          float* __restrict__ dst,
                          __nv_bfloat16* __restrict__ ohi,
                          __nv_bfloat16* __restrict__ olo)
{
    int row = blockIdx.x;
    int tid = threadIdx.x;   // 256
    __shared__ float red[8];
    const float* xr = x + (size_t)row * Esz;
    const float* dr = dlt + (size_t)row * Esz;
    float v0 = xr[tid] + dr[tid];
    float v1 = xr[tid + 256] + dr[tid + 256];
    float s = v0 + v1;
    #pragma unroll
    for (int o = 16; o; o >>= 1) s += __shfl_xor_sync(0xffffffffu, s, o);
    if ((tid & 31) == 0) red[tid >> 5] = s;
    __syncthreads();
    float mean = 0.f;
    #pragma unroll
    for (int w = 0; w < 8; w++) mean += red[w];
    mean *= (1.f / 512.f);
    __syncthreads();
    float e0 = v0 - mean, e1 = v1 - mean;
    float s2 = e0 * e0 + e1 * e1;
    #pragma unroll
    for (int o = 16; o; o >>= 1) s2 += __shfl_xor_sync(0xffffffffu, s2, o);
    if ((tid & 31) == 0) red[tid >> 5] = s2;
    __syncthreads();
    float var = 0.f;
    #pragma unroll
    for (int w = 0; w < 8; w++) var += red[w];
    var *= (1.f / 512.f);
    float rstd = rsqrtf(var + 1e-5f);
    float o0 = e0 * rstd * g[tid] + bt[tid];
    float o1 = e1 * rstd * g[tid + 256] + bt[tid + 256];
    size_t i0 = (size_t)row * Esz + tid;
    size_t i1 = i0 + 256;
    dst[i0] = o0;
    dst[i1] = o1;
    unsigned short hv, lv;
    split1(o0, hv, lv);
    ohi[i0] = __ushort_as_bfloat16(hv); olo[i0] = __ushort_as_bfloat16(lv);
    split1(o1, hv, lv);
    ohi[i1] = __ushort_as_bfloat16(hv); olo[i1] = __ushort_as_bfloat16(lv);
}

// ===================== host orchestration ===================================
extern "C" void kernel_launch(void* const* d_in, const int* in_sizes, int n_in,
                              void* d_out, int out_size)
{
    const float* x        = (const float*)d_in[0];
    const int*   adj      = (const int*)d_in[1];
    const int*   smk      = (const int*)d_in[2];
    const int*   omk      = (const int*)d_in[3];
    const float* knowledge= (const float*)d_in[4];
    const int*   know_adj = (const int*)d_in[5];
    const int*   pos_mask = (const int*)d_in[6];
    const float* pe_k     = (const float*)d_in[7];
    const float* pe_v     = (const float*)d_in[8];
    const float* Wq       = (const float*)d_in[9];
    const float* Wk       = (const float*)d_in[10];
    const float* Wvs      = (const float*)d_in[11];
    const float* Wvo      = (const float*)d_in[12];
    const float* Wo       = (const float*)d_in[13];
    const float* Wkn      = (const float*)d_in[14];
    const float* ln1g     = (const float*)d_in[15];
    const float* ln1b     = (const float*)d_in[16];
    const float* w1       = (const float*)d_in[17];
    const float* b1       = (const float*)d_in[18];
    const float* w2       = (const float*)d_in[19];
    const float* b2       = (const float*)d_in[20];
    const float* ln2g     = (const float*)d_in[21];
    const float* ln2b     = (const float*)d_in[22];
    float* out = (float*)d_out;

    float *h, *qkv, *kproj, *A1, *A2, *ap, *asum, *tmp, *ff;
    cudaGetSymbolAddress((void**)&h, g_h);
    cudaGetSymbolAddress((void**)&qkv, g_qkv);
    cudaGetSymbolAddress((void**)&kproj, g_kproj);
    cudaGetSymbolAddress((void**)&A1, g_A1);
    cudaGetSymbolAddress((void**)&A2, g_A2);
    cudaGetSymbolAddress((void**)&ap, g_ap);
    cudaGetSymbolAddress((void**)&asum, g_attnsum);
    cudaGetSymbolAddress((void**)&tmp, g_tmp);
    cudaGetSymbolAddress((void**)&ff, g_ff);

    __nv_bfloat16 *h_hi, *h_lo, *as_hi, *as_lo, *ff_hi, *ff_lo, *kn_hi, *kn_lo;
    __nv_bfloat16 *wq_hi, *wq_lo, *wk_hi, *wk_lo, *wvs_hi, *wvs_lo, *wvo_hi, *wvo_lo;
    __nv_bfloat16 *wo_hi, *wo_lo, *wkn_hi, *wkn_lo, *w1_hi, *w1_lo, *w2_hi, *w2_lo;
    cudaGetSymbolAddress((void**)&h_hi, g_h_hi);   cudaGetSymbolAddress((void**)&h_lo, g_h_lo);
    cudaGetSymbolAddress((void**)&as_hi, g_as_hi); cudaGetSymbolAddress((void**)&as_lo, g_as_lo);
    cudaGetSymbolAddress((void**)&ff_hi, g_ff_hi); cudaGetSymbolAddress((void**)&ff_lo, g_ff_lo);
    cudaGetSymbolAddress((void**)&kn_hi, g_kn_hi); cudaGetSymbolAddress((void**)&kn_lo, g_kn_lo);
    cudaGetSymbolAddress((void**)&wq_hi, g_Wq_hi); cudaGetSymbolAddress((void**)&wq_lo, g_Wq_lo);
    cudaGetSymbolAddress((void**)&wk_hi, g_Wk_hi); cudaGetSymbolAddress((void**)&wk_lo, g_Wk_lo);
    cudaGetSymbolAddress((void**)&wvs_hi, g_Wvs_hi); cudaGetSymbolAddress((void**)&wvs_lo, g_Wvs_lo);
    cudaGetSymbolAddress((void**)&wvo_hi, g_Wvo_hi); cudaGetSymbolAddress((void**)&wvo_lo, g_Wvo_lo);
    cudaGetSymbolAddress((void**)&wo_hi, g_Wo_hi); cudaGetSymbolAddress((void**)&wo_lo, g_Wo_lo);
    cudaGetSymbolAddress((void**)&wkn_hi, g_Wkn_hi); cudaGetSymbolAddress((void**)&wkn_lo, g_Wkn_lo);
    cudaGetSymbolAddress((void**)&w1_hi, g_w1_hi); cudaGetSymbolAddress((void**)&w1_lo, g_w1_lo);
    cudaGetSymbolAddress((void**)&w2_hi, g_w2_hi); cudaGetSymbolAddress((void**)&w2_lo, g_w2_lo);

    cudaFuncSetAttribute(gemm_tc, cudaFuncAttributeMaxDynamicSharedMemorySize, GEMM_SMEM);
    cudaFuncSetAttribute(gemm_tc4, cudaFuncAttributeMaxDynamicSharedMemorySize, GEMM_SMEM);

    // -------- one-time conversions (captured in graph, deterministic) -------
    const int nEE4 = Lnum * Esz * Esz / 4;
    const int nFE4 = Lnum * FFsz * Esz / 4;
    cvt_kernel<<<(nEE4 + 255) / 256, 256>>>(Wq,  nullptr, wq_hi,  wq_lo,  nEE4);
    cvt_kernel<<<(nEE4 + 255) / 256, 256>>>(Wk,  nullptr, wk_hi,  wk_lo,  nEE4);
    cvt_kernel<<<(nEE4 + 255) / 256, 256>>>(Wvs, nullptr, wvs_hi, wvs_lo, nEE4);
    cvt_kernel<<<(nEE4 + 255) / 256, 256>>>(Wvo, nullptr, wvo_hi, wvo_lo, nEE4);
    cvt_kernel<<<(nEE4 + 255) / 256, 256>>>(Wo,  nullptr, wo_hi,  wo_lo,  nEE4);
    cvt_kernel<<<(nEE4 + 255) / 256, 256>>>(Wkn, nullptr, wkn_hi, wkn_lo, nEE4);
    cvt_kernel<<<(nFE4 + 255) / 256, 256>>>(w1,  nullptr, w1_hi,  w1_lo,  nFE4);
    cvt_kernel<<<(nFE4 + 255) / 256, 256>>>(w2,  nullptr, w2_hi,  w2_lo,  nFE4);
    cvt_kernel<<<(1000 * Esz / 4 + 255) / 256, 256>>>(knowledge, nullptr, kn_hi, kn_lo,
                                                      1000 * Esz / 4);
    cvt_kernel<<<(Msz * Esz / 4 + 255) / 256, 256>>>(x, h, h_hi, h_lo, Msz * Esz / 4);

    const size_t EE = (size_t)Esz * Esz;
    const size_t FE = (size_t)FFsz * Esz;
    for (int l = 0; l < Lnum; l++) {
        size_t oW = (size_t)l * EE;
        size_t oF = (size_t)l * FE;

        gemm_tc4<<<dim3(4, 4, 4), 256, GEMM_SMEM>>>(
            h_hi, h_lo,
            wq_hi + oW,  wq_lo + oW,  wk_hi + oW,  wk_lo + oW,
            wvs_hi + oW, wvs_lo + oW, wvo_hi + oW, wvo_lo + oW,
            qkv, Msz, Esz, Esz);
        gemm_tc<<<dim3(4, 8), 256, GEMM_SMEM>>>(
            kn_hi, kn_lo, wkn_hi + oW, wkn_lo + oW, nullptr, kproj,
            nullptr, nullptr, 1000, Esz, Esz, 0);
        scores_kernel<<<dim3(Ssz, Bsz), 256>>>(
            qkv, qkv + (size_t)Msz * Esz, kproj, know_adj, pos_mask, adj, smk, omk,
            pe_k, A1, A2, ap);
        attnsum_kernel<<<dim3(4, Hn, Bsz), 256>>>(
            qkv + 2 * (size_t)Msz * Esz, qkv + 3 * (size_t)Msz * Esz,
            A1, A2, ap, pe_v, asum, as_hi, as_lo);
        gemm_tc<<<dim3(4, 4), 256, GEMM_SMEM>>>(
            as_hi, as_lo, wo_hi + oW, wo_lo + oW, nullptr, tmp,
            nullptr, nullptr, Msz, Esz, Esz, 0);
        ln_kernel<<<Msz, 256>>>(h, tmp, ln1g + l * Esz, ln1b + l * Esz, h, h_hi, h_lo);
        gemm_tc<<<dim3(16, 4), 256, GEMM_SMEM>>>(
            h_hi, h_lo, w1_hi + oF, w1_lo + oF, b1 + (size_t)l * FFsz, ff,
            ff_hi, ff_lo, Msz, FFsz, Esz, 1);
        gemm_tc<<<dim3(4, 4), 256, GEMM_SMEM>>>(
            ff_hi, ff_lo, w2_hi + oF, w2_lo + oF, b2 + (size_t)l * Esz, tmp,
            nullptr, nullptr, Msz, Esz, FFsz, 0);
        float* dst = (l == Lnum - 1) ? out : h;
        ln_kernel<<<Msz, 256>>>(h, tmp, ln2g + l * Esz, ln2b + l * Esz, dst, h_hi, h_lo);
    }
}

// round 6
// speedup vs baseline: 1.4499x; 1.4499x over previous
#include <cuda_runtime.h>
#include <cuda_bf16.h>
#include <cstdint>

#define Bsz 4
#define Ssz 128
#define Esz 512
#define Hn 8
#define HDsz 64
#define FFsz 2048
#define Lnum 4
#define Msz (Bsz*Ssz)   /* 512 rows */

// ===================== scratch (static device memory) ======================
__device__ float g_h[Msz*Esz];
__device__ float g_qkv[4*Msz*Esz];
__device__ float g_kproj[1024*Esz];
__device__ float g_A1[Bsz*Hn*Ssz*Ssz];
__device__ float g_A2[Bsz*Hn*Ssz*Ssz];
__device__ float g_ap[Bsz*Hn*Ssz*11];
__device__ float g_attnsum[Msz*Esz];
__device__ float g_tmp[Msz*Esz];
__device__ float g_ff[Msz*FFsz];
__device__ float g_part[4*512*512];   // split-K partials

// ===================== helpers ==============================================
__device__ __forceinline__ void split1(float x, unsigned short& h, unsigned short& l)
{
    __nv_bfloat16 hb = __float2bfloat16(x);
    h = __bfloat16_as_ushort(hb);
    l = __bfloat16_as_ushort(__float2bfloat16(x - __bfloat162float(hb)));
}
__device__ __forceinline__ void ldsm_x4(uint32_t& r0, uint32_t& r1,
                                        uint32_t& r2, uint32_t& r3, uint32_t addr)
{
    asm volatile("ldmatrix.sync.aligned.m8n8.x4.shared.b16 {%0,%1,%2,%3}, [%4];"
                 : "=r"(r0), "=r"(r1), "=r"(r2), "=r"(r3) : "r"(addr));
}
__device__ __forceinline__ void mma_bf16(float* c, const uint32_t* a, const uint32_t* b)
{
    asm volatile("mma.sync.aligned.m16n8k16.row.col.f32.bf16.bf16.f32 "
                 "{%0,%1,%2,%3},{%4,%5,%6,%7},{%8,%9},{%0,%1,%2,%3};"
                 : "+f"(c[0]), "+f"(c[1]), "+f"(c[2]), "+f"(c[3])
                 : "r"(a[0]), "r"(a[1]), "r"(a[2]), "r"(a[3]), "r"(b[0]), "r"(b[1]));
}
__device__ __forceinline__ uint32_t smem_u32(const void* p) {
    uint32_t a;
    asm("{ .reg .u64 t; cvta.to.shared.u64 t, %1; cvt.u32.u64 %0, t; }" : "=r"(a) : "l"(p));
    return a;
}

// ===================== tensor-core bf16x3 GEMM ==============================
// C[M,N] = A[M,K] @ W[N,K]^T, fp32 in/out, in-kernel hi/lo bf16 split.
// 64x64 CTA tile, 128 threads (4 warps, 2m x 2n, warp tile 32x32), BK=32.
#define BK 32
#define LDSE 40                 /* bf16 elems per smem row (80 B, cf-free) */
#define PARTB (64*LDSE*2)       /* 5120 B per matrix part */
// smem parts: A_hi, A_lo, B_hi, B_lo -> 20480 B total (static)

// stage 64 rows x 32 cols fp32 -> split -> smem bf16 hi/lo
__device__ __forceinline__ void stage_split(
    const float* __restrict__ src, int row0, int rows_tot, int k0, int K,
    uint32_t s_hi, uint32_t s_lo, int tid)
{
    int r = tid >> 1, half = tid & 1;
    int gr = min(row0 + r, rows_tot - 1);
    const float4* p = (const float4*)(src + (size_t)gr * K + k0 + half * 16);
    uint32_t off = (uint32_t)r * (LDSE * 2) + half * 32;
    #pragma unroll
    for (int u = 0; u < 4; u++) {
        float4 v = p[u];
        ushort4 hh, ll;
        split1(v.x, hh.x, ll.x); split1(v.y, hh.y, ll.y);
        split1(v.z, hh.z, ll.z); split1(v.w, hh.w, ll.w);
        asm volatile("st.shared.v4.u16 [%0], {%1,%2,%3,%4};"
                     :: "r"(s_hi + off + u * 8), "h"(hh.x), "h"(hh.y), "h"(hh.z), "h"(hh.w));
        asm volatile("st.shared.v4.u16 [%0], {%1,%2,%3,%4};"
                     :: "r"(s_lo + off + u * 8), "h"(ll.x), "h"(ll.y), "h"(ll.z), "h"(ll.w));
    }
}

__device__ __forceinline__ void gemm_mma_body(
    const float* __restrict__ A, const float* __restrict__ W,
    const float* __restrict__ bias, float* __restrict__ C,
    int M, int N, int kbeg, int kend, int K, int act)
{
    __shared__ __align__(16) char smem[4 * PARTB];
    uint32_t sb = smem_u32(smem);
    int tid = threadIdx.x;                  // 128
    int lane = tid & 31, wid = tid >> 5;
    int wm = wid >> 1, wn = wid & 1;        // 2 x 2 warps, warp tile 32x32
    int bm = blockIdx.y * 64, bn = blockIdx.x * 64;

    float acc[2][4][4] = {};

    // fragment byte offsets (within a part)
    uint32_t a_off = ((uint32_t)(wm * 32 + (lane & 15)) * LDSE + ((lane & 16) >> 1)) * 2;
    uint32_t b_off = ((uint32_t)(wn * 32 + (lane & 7) + ((lane & 16) >> 1)) * LDSE) * 2
                     + (lane & 8) * 2;

    for (int k0 = kbeg; k0 < kend; k0 += BK) {
        stage_split(A, bm, M, k0, K, sb, sb + PARTB, tid);
        stage_split(W, bn, N, k0, K, sb + 2 * PARTB, sb + 3 * PARTB, tid);
        __syncthreads();
        #pragma unroll
        for (int ks = 0; ks < 2; ks++) {
            uint32_t a_hi[2][4], a_lo[2][4], b_hi[4][2], b_lo[4][2];
            #pragma unroll
            for (int tm = 0; tm < 2; tm++) {
                uint32_t ad = sb + a_off + (uint32_t)tm * 16 * LDSE * 2 + ks * 32;
                ldsm_x4(a_hi[tm][0], a_hi[tm][1], a_hi[tm][2], a_hi[tm][3], ad);
                ldsm_x4(a_lo[tm][0], a_lo[tm][1], a_lo[tm][2], a_lo[tm][3], ad + PARTB);
            }
            #pragma unroll
            for (int tp = 0; tp < 2; tp++) {
                uint32_t bd = sb + 2 * PARTB + b_off
                            + (uint32_t)tp * 16 * LDSE * 2 + ks * 32;
                ldsm_x4(b_hi[2*tp][0], b_hi[2*tp][1], b_hi[2*tp+1][0], b_hi[2*tp+1][1], bd);
                ldsm_x4(b_lo[2*tp][0], b_lo[2*tp][1], b_lo[2*tp+1][0], b_lo[2*tp+1][1],
                        bd + PARTB);
            }
            #pragma unroll
            for (int tm = 0; tm < 2; tm++)
                #pragma unroll
                for (int tn = 0; tn < 4; tn++) {
                    mma_bf16(acc[tm][tn], a_hi[tm], b_hi[tn]);
                    mma_bf16(acc[tm][tn], a_hi[tm], b_lo[tn]);
                    mma_bf16(acc[tm][tn], a_lo[tm], b_hi[tn]);
                }
        }
        __syncthreads();
    }

    // epilogue
    int mrow = bm + wm * 32 + (lane >> 2);
    int ncol = bn + wn * 32 + (lane & 3) * 2;
    #pragma unroll
    for (int tm = 0; tm < 2; tm++) {
        #pragma unroll
        for (int half = 0; half < 2; half++) {
            int m = mrow + tm * 16 + half * 8;
            if (m >= M) continue;
            size_t rb = (size_t)m * N;
            #pragma unroll
            for (int tn = 0; tn < 4; tn++) {
                int n = ncol + tn * 8;
                float v0 = acc[tm][tn][half * 2 + 0];
                float v1 = acc[tm][tn][half * 2 + 1];
                if (bias) { v0 += bias[n]; v1 += bias[n + 1]; }
                if (act) { v0 = fmaxf(v0, 0.f); v1 = fmaxf(v1, 0.f); }
                *(float2*)(C + rb + n) = make_float2(v0, v1);
            }
        }
    }
}

__global__ void __launch_bounds__(128) gemm_tc(
    const float* A, const float* W, const float* bias, float* C,
    int M, int N, int K, int act)
{
    gemm_mma_body(A, W, bias, C, M, N, 0, K, K, act);
}

__global__ void __launch_bounds__(128) gemm_tc_splitk(
    const float* A, const float* W, float* part, int M, int N, int K, int KS)
{
    int chunk = K / KS;
    int z = blockIdx.z;
    gemm_mma_body(A, W, nullptr, part + (size_t)z * M * N,
                  M, N, z * chunk, (z + 1) * chunk, K, 0);
}

__global__ void __launch_bounds__(128) gemm_tc4(
    const float* A, const float* W0, const float* W1,
    const float* W2, const float* W3, float* C, int M, int N, int K)
{
    int z = blockIdx.z;
    const float* W = (z == 0) ? W0 : (z == 1) ? W1 : (z == 2) ? W2 : W3;
    gemm_mma_body(A, W, nullptr, C + (size_t)z * M * N, M, N, 0, K, K, 0);
}

// deterministic split-K reduce (+bias, +relu)
__global__ void reduce_kernel(const float* __restrict__ part, const float* __restrict__ bias,
                              float* __restrict__ C, int MN, int N, int KS, int act)
{
    int i = (blockIdx.x * 256 + threadIdx.x) * 4;
    if (i >= MN) return;
    float4 s = *(const float4*)(part + i);
    for (int z = 1; z < KS; z++) {
        float4 t = *(const float4*)(part + (size_t)z * MN + i);
        s.x += t.x; s.y += t.y; s.z += t.z; s.w += t.w;
    }
    if (bias) {
        int n = i % N;
        s.x += bias[n]; s.y += bias[n + 1]; s.z += bias[n + 2]; s.w += bias[n + 3];
    }
    if (act) {
        s.x = fmaxf(s.x, 0.f); s.y = fmaxf(s.y, 0.f);
        s.z = fmaxf(s.z, 0.f); s.w = fmaxf(s.w, 0.f);
    }
    *(float4*)(C + i) = s;
}

// ======== fused scores + softmax + mask-split + pos-histogram ==============
__global__ void scores_kernel(const float* __restrict__ q, const float* __restrict__ k,
                              const float* __restrict__ kproj,
                              const int* __restrict__ know_adj,
                              const int* __restrict__ pos_mask,
                              const int* __restrict__ adj,
                              const int* __restrict__ smk, const int* __restrict__ omk,
                              const float* __restrict__ pe_k,
                              float* __restrict__ A1, float* __restrict__ A2,
                              float* __restrict__ attn_pos)
{
    int i = blockIdx.x, b = blockIdx.y;
    int tid = threadIdx.x;                  // 0..255
    __shared__ float q_sh[512];
    __shared__ float sc[8 * 128];
    __shared__ float qr[8 * 11];
    __shared__ int   ka_sh[128];
    __shared__ int   p_sh[128];

    q_sh[tid]       = q[(size_t)(b * Ssz + i) * Esz + tid];
    q_sh[tid + 256] = q[(size_t)(b * Ssz + i) * Esz + tid + 256];
    if (tid < 128) {
        int ka = know_adj[(size_t)(b * Ssz + i) * Ssz + tid];
        ka_sh[tid] = min(max(ka, 0), 999);
        int p = pos_mask[i * Ssz + tid];
        p_sh[tid] = min(max(p, 0), 10);
    }
    __syncthreads();

    {
        int j  = tid & 127;
        int hb = tid >> 7;
        const float4* krow = (const float4*)(k + (size_t)(b * Ssz + j) * Esz + hb * 256);
        const float4* kprow = (const float4*)(kproj + (size_t)ka_sh[j] * Esz + hb * 256);
        const float4* qv = (const float4*)(q_sh + hb * 256);
        #pragma unroll
        for (int hh = 0; hh < 4; hh++) {
            float a = 0.f;
            #pragma unroll
            for (int u = 0; u < 16; u++) {
                int v = hh * 16 + u;
                float4 kv = krow[v];
                float4 kp = kprow[v];
                float4 qq = qv[v];
                a += qq.x * (kv.x + kp.x) + qq.y * (kv.y + kp.y)
                   + qq.z * (kv.z + kp.z) + qq.w * (kv.w + kp.w);
            }
            sc[(4 * hb + hh) * 128 + j] = a;
        }
    }
    if (tid < 88) {
        int h = tid / 11, p = tid % 11;
        float s = 0.f;
        const float4* pk = (const float4*)(pe_k + p * HDsz);
        const float4* qv = (const float4*)(q_sh + h * 64);
        #pragma unroll
        for (int v = 0; v < 16; v++) {
            float4 e = pk[v], qq = qv[v];
            s += qq.x * e.x + qq.y * e.y + qq.z * e.z + qq.w * e.w;
        }
        qr[h * 11 + p] = s;
    }
    __syncthreads();

    {
        int w = tid >> 5, l = tid & 31;
        float s[4];
        float m = -3.4e38f;
        #pragma unroll
        for (int t = 0; t < 4; t++) {
            int j = l + 32 * t;
            float ss = (sc[w * 128 + j] + qr[w * 11 + p_sh[j]]) * 0.125f;
            if (adj[(size_t)(b * Ssz + i) * Ssz + j] == 0) ss -= 1e30f;
            s[t] = ss;
            m = fmaxf(m, ss);
        }
        #pragma unroll
        for (int o = 16; o; o >>= 1) m = fmaxf(m, __shfl_xor_sync(0xffffffffu, m, o));
        float sum = 0.f;
        float e[4];
        #pragma unroll
        for (int t = 0; t < 4; t++) { e[t] = __expf(s[t] - m); sum += e[t]; }
        #pragma unroll
        for (int o = 16; o; o >>= 1) sum += __shfl_xor_sync(0xffffffffu, sum, o);
        float inv = 1.f / sum;
        size_t rbase = ((size_t)(b * Hn + w) * Ssz + i) * Ssz;
        #pragma unroll
        for (int t = 0; t < 4; t++) {
            int j = l + 32 * t;
            float attn = e[t] * inv;
            A1[rbase + j] = attn * (float)smk[(size_t)(b * Ssz + i) * Ssz + j];
            A2[rbase + j] = attn * (float)omk[(size_t)(b * Ssz + i) * Ssz + j];
            sc[w * 128 + j] = attn;
        }
    }
    __syncthreads();

    if (tid < 88) {
        int h = tid / 11, p = tid % 11;
        float s = 0.f;
        for (int j = 0; j < 128; j++)
            if (p_sh[j] == p) s += sc[h * 128 + j];
        attn_pos[((size_t)(b * Hn + h) * Ssz + i) * 11 + p] = s;
    }
}

// ================= attention value sum ======================================
__global__ void attnsum_kernel(const float* __restrict__ vs, const float* __restrict__ vo,
                               const float* __restrict__ A1, const float* __restrict__ A2,
                               const float* __restrict__ attn_pos,
                               const float* __restrict__ pe_v,
                               float* __restrict__ outbuf)
{
    int itile = blockIdx.x, hh = blockIdx.y, b = blockIdx.z;
    int tid = threadIdx.x;
    int grp = tid >> 6, d = tid & 63;
    __shared__ float vsh[128 * 65];

    for (int idx = tid; idx < 128 * 64; idx += 256) {
        int j = idx >> 6, dd = idx & 63;
        vsh[j * 65 + dd] = vs[(size_t)(b * Ssz + j) * Esz + hh * HDsz + dd];
    }
    __syncthreads();

    float acc[8];
    #pragma unroll
    for (int it = 0; it < 8; it++) {
        int i = itile * 32 + it * 4 + grp;
        const float* a1 = A1 + ((size_t)(b * Hn + hh) * Ssz + i) * Ssz;
        float s = 0.f;
        #pragma unroll 4
        for (int jj = 0; jj < 128; jj++) s += a1[jj] * vsh[jj * 65 + d];
        acc[it] = s;
    }
    __syncthreads();
    for (int idx = tid; idx < 128 * 64; idx += 256) {
        int j = idx >> 6, dd = idx & 63;
        vsh[j * 65 + dd] = vo[(size_t)(b * Ssz + j) * Esz + hh * HDsz + dd];
    }
    __syncthreads();
    #pragma unroll
    for (int it = 0; it < 8; it++) {
        int i = itile * 32 + it * 4 + grp;
        const float* a2 = A2 + ((size_t)(b * Hn + hh) * Ssz + i) * Ssz;
        float s = acc[it];
        #pragma unroll 4
        for (int jj = 0; jj < 128; jj++) s += a2[jj] * vsh[jj * 65 + d];
        const float* app = attn_pos + ((size_t)(b * Hn + hh) * Ssz + i) * 11;
        #pragma unroll
        for (int p = 0; p < 11; p++) s += app[p] * pe_v[p * HDsz + d];
        outbuf[(size_t)(b * Ssz + i) * Esz + hh * HDsz + d] = s;
    }
}

// ============== residual + layernorm ========================================
__global__ void ln_kernel(const float* __restrict__ x, const float* __restrict__ dlt,
                          const float* __restrict__ g, const float* __restrict__ bt,
                          float* __restrict__ dst)
{
    int row = blockIdx.x;
    int tid = threadIdx.x;   // 256
    __shared__ float red[8];
    const float* xr = x + (size_t)row * Esz;
    const float* dr = dlt + (size_t)row * Esz;
    float v0 = xr[tid] + dr[tid];
    float v1 = xr[tid + 256] + dr[tid + 256];
    float s = v0 + v1;
    #pragma unroll
    for (int o = 16; o; o >>= 1) s += __shfl_xor_sync(0xffffffffu, s, o);
    if ((tid & 31) == 0) red[tid >> 5] = s;
    __syncthreads();
    float mean = 0.f;
    #pragma unroll
    for (int w = 0; w < 8; w++) mean += red[w];
    mean *= (1.f / 512.f);
    __syncthreads();
    float e0 = v0 - mean, e1 = v1 - mean;
    float s2 = e0 * e0 + e1 * e1;
    #pragma unroll
    for (int o = 16; o; o >>= 1) s2 += __shfl_xor_sync(0xffffffffu, s2, o);
    if ((tid & 31) == 0) red[tid >> 5] = s2;
    __syncthreads();
    float var = 0.f;
    #pragma unroll
    for (int w = 0; w < 8; w++) var += red[w];
    var *= (1.f / 512.f);
    float rstd = rsqrtf(var + 1e-5f);
    dst[(size_t)row * Esz + tid]       = e0 * rstd * g[tid] + bt[tid];
    dst[(size_t)row * Esz + 256 + tid] = e1 * rstd * g[tid + 256] + bt[tid + 256];
}

__global__ void copy_kernel(float* __restrict__ dst, const float* __restrict__ src, int n)
{
    int i = blockIdx.x * blockDim.x + threadIdx.x;
    if (i < n) dst[i] = src[i];
}

// ===================== host orchestration ===================================
extern "C" void kernel_launch(void* const* d_in, const int* in_sizes, int n_in,
                              void* d_out, int out_size)
{
    const float* x        = (const float*)d_in[0];
    const int*   adj      = (const int*)d_in[1];
    const int*   smk      = (const int*)d_in[2];
    const int*   omk      = (const int*)d_in[3];
    const float* knowledge= (const float*)d_in[4];
    const int*   know_adj = (const int*)d_in[5];
    const int*   pos_mask = (const int*)d_in[6];
    const float* pe_k     = (const float*)d_in[7];
    const float* pe_v     = (const float*)d_in[8];
    const float* Wq       = (const float*)d_in[9];
    const float* Wk       = (const float*)d_in[10];
    const float* Wvs      = (const float*)d_in[11];
    const float* Wvo      = (const float*)d_in[12];
    const float* Wo       = (const float*)d_in[13];
    const float* Wkn      = (const float*)d_in[14];
    const float* ln1g     = (const float*)d_in[15];
    const float* ln1b     = (const float*)d_in[16];
    const float* w1       = (const float*)d_in[17];
    const float* b1       = (const float*)d_in[18];
    const float* w2       = (const float*)d_in[19];
    const float* b2       = (const float*)d_in[20];
    const float* ln2g     = (const float*)d_in[21];
    const float* ln2b     = (const float*)d_in[22];
    float* out = (float*)d_out;

    float *h, *qkv, *kproj, *A1, *A2, *ap, *asum, *tmp, *ff, *part;
    cudaGetSymbolAddress((void**)&h, g_h);
    cudaGetSymbolAddress((void**)&qkv, g_qkv);
    cudaGetSymbolAddress((void**)&kproj, g_kproj);
    cudaGetSymbolAddress((void**)&A1, g_A1);
    cudaGetSymbolAddress((void**)&A2, g_A2);
    cudaGetSymbolAddress((void**)&ap, g_ap);
    cudaGetSymbolAddress((void**)&asum, g_attnsum);
    cudaGetSymbolAddress((void**)&tmp, g_tmp);
    cudaGetSymbolAddress((void**)&ff, g_ff);
    cudaGetSymbolAddress((void**)&part, g_part);

    copy_kernel<<<(Msz * Esz + 255) / 256, 256>>>(h, x, Msz * Esz);

    const size_t EE = (size_t)Esz * Esz;
    const size_t FE = (size_t)FFsz * Esz;
    for (int l = 0; l < Lnum; l++) {
        const float* wq  = Wq  + (size_t)l * EE;
        const float* wk  = Wk  + (size_t)l * EE;
        const float* wvs = Wvs + (size_t)l * EE;
        const float* wvo = Wvo + (size_t)l * EE;
        const float* wo  = Wo  + (size_t)l * EE;
        const float* wkn = Wkn + (size_t)l * EE;

        // q,k,vs,vo projections (256 CTAs)
        gemm_tc4<<<dim3(8, 8, 4), 128>>>(h, wq, wk, wvs, wvo, qkv, Msz, Esz, Esz);
        // knowledge projection table [1000, 512] (128 CTAs)
        gemm_tc<<<dim3(8, 16), 128>>>(knowledge, wkn, nullptr, kproj, 1000, Esz, Esz, 0);
        // fused scores / softmax / mask-split / pos histogram
        scores_kernel<<<dim3(Ssz, Bsz), 256>>>(
            qkv, qkv + (size_t)Msz * Esz, kproj, know_adj, pos_mask, adj, smk, omk,
            pe_k, A1, A2, ap);
        // attention value sum
        attnsum_kernel<<<dim3(4, Hn, Bsz), 256>>>(
            qkv + 2 * (size_t)Msz * Esz, qkv + 3 * (size_t)Msz * Esz,
            A1, A2, ap, pe_v, asum);
        // output projection, split-K=2 (128 CTAs)
        gemm_tc_splitk<<<dim3(8, 8, 2), 128>>>(asum, wo, part, Msz, Esz, Esz, 2);
        reduce_kernel<<<(Msz * Esz / 4 + 255) / 256, 256>>>(part, nullptr, tmp,
                                                            Msz * Esz, Esz, 2, 0);
        // residual + LN1
        ln_kernel<<<Msz, 256>>>(h, tmp, ln1g + l * Esz, ln1b + l * Esz, h);
        // FFN1 (256 CTAs, fused bias+relu)
        gemm_tc<<<dim3(32, 8), 128>>>(h, w1 + (size_t)l * FE, b1 + (size_t)l * FFsz,
                                      ff, Msz, FFsz, Esz, 1);
        // FFN2, split-K=4 (256 CTAs)
        gemm_tc_splitk<<<dim3(8, 8, 4), 128>>>(ff, w2 + (size_t)l * FE, part,
                                               Msz, Esz, FFsz, 4);
        reduce_kernel<<<(Msz * Esz / 4 + 255) / 256, 256>>>(part, b2 + l * Esz, tmp,
                                                            Msz * Esz, Esz, 4, 0);
        // residual + LN2 (final layer -> d_out)
        float* dst = (l == Lnum - 1) ? out : h;
        ln_kernel<<<Msz, 256>>>(h, tmp, ln2g + l * Esz, ln2b + l * Esz, dst);
    }
}

// round 7
// speedup vs baseline: 1.6757x; 1.1557x over previous
#include <cuda_runtime.h>
#include <cuda_bf16.h>
#include <cstdint>

#define Bsz 4
#define Ssz 128
#define Esz 512
#define Hn 8
#define HDsz 64
#define FFsz 2048
#define Lnum 4
#define Msz (Bsz*Ssz)   /* 512 rows */

// ===================== scratch (static device memory) ======================
__device__ float g_h[Msz*Esz];
__device__ float g_qkv[4*Msz*Esz];
__device__ float g_kproj[1024*Esz];
__device__ float g_A1[Bsz*Hn*Ssz*Ssz];
__device__ float g_A2[Bsz*Hn*Ssz*Ssz];
__device__ float g_ap[Bsz*Hn*Ssz*11];
__device__ float g_attnsum[Msz*Esz];
__device__ float g_tmp[Msz*Esz];
__device__ float g_ff[Msz*FFsz];
__device__ float g_part[4*512*512];     // split-K partials / qk buffer
__device__ float g_qkp[512*8000];       // qkp[b,i,r,h]  (16 MB)

// ===================== helpers ==============================================
__device__ __forceinline__ void split1(float x, unsigned short& h, unsigned short& l)
{
    __nv_bfloat16 hb = __float2bfloat16(x);
    h = __bfloat16_as_ushort(hb);
    l = __bfloat16_as_ushort(__float2bfloat16(x - __bfloat162float(hb)));
}
__device__ __forceinline__ void ldsm_x4(uint32_t& r0, uint32_t& r1,
                                        uint32_t& r2, uint32_t& r3, uint32_t addr)
{
    asm volatile("ldmatrix.sync.aligned.m8n8.x4.shared.b16 {%0,%1,%2,%3}, [%4];"
                 : "=r"(r0), "=r"(r1), "=r"(r2), "=r"(r3) : "r"(addr));
}
__device__ __forceinline__ void mma_bf16(float* c, const uint32_t* a, const uint32_t* b)
{
    asm volatile("mma.sync.aligned.m16n8k16.row.col.f32.bf16.bf16.f32 "
                 "{%0,%1,%2,%3},{%4,%5,%6,%7},{%8,%9},{%0,%1,%2,%3};"
                 : "+f"(c[0]), "+f"(c[1]), "+f"(c[2]), "+f"(c[3])
                 : "r"(a[0]), "r"(a[1]), "r"(a[2]), "r"(a[3]), "r"(b[0]), "r"(b[1]));
}
__device__ __forceinline__ uint32_t smem_u32(const void* p) {
    uint32_t a;
    asm("{ .reg .u64 t; cvta.to.shared.u64 t, %1; cvt.u32.u64 %0, t; }" : "=r"(a) : "l"(p));
    return a;
}

// ===================== tensor-core bf16x3 GEMM ==============================
// C[m,n] = sum_k A[m, kbeg..kend) * W[n, kbeg..kend), strided in/out.
// 64x64 CTA tile, 128 threads (2m x 2n warps, warp tile 32x32), BK=32.
#define BK 32
#define LDSE 40                 /* bf16 elems per smem row (80 B) */
#define PARTB (64*LDSE*2)       /* 5120 B per matrix part */

__device__ __forceinline__ void stage_split(
    const float* __restrict__ src, int lda, int row0, int rows_tot, int k0,
    uint32_t s_hi, uint32_t s_lo, int tid)
{
    int r = tid >> 1, half = tid & 1;
    int gr = min(row0 + r, rows_tot - 1);
    const float4* p = (const float4*)(src + (size_t)gr * lda + k0 + half * 16);
    uint32_t off = (uint32_t)r * (LDSE * 2) + half * 32;
    #pragma unroll
    for (int u = 0; u < 4; u++) {
        float4 v = p[u];
        ushort4 hh, ll;
        split1(v.x, hh.x, ll.x); split1(v.y, hh.y, ll.y);
        split1(v.z, hh.z, ll.z); split1(v.w, hh.w, ll.w);
        asm volatile("st.shared.v4.u16 [%0], {%1,%2,%3,%4};"
                     :: "r"(s_hi + off + u * 8), "h"(hh.x), "h"(hh.y), "h"(hh.z), "h"(hh.w));
        asm volatile("st.shared.v4.u16 [%0], {%1,%2,%3,%4};"
                     :: "r"(s_lo + off + u * 8), "h"(ll.x), "h"(ll.y), "h"(ll.z), "h"(ll.w));
    }
}

__device__ __forceinline__ void gemm_mma_body(
    const float* __restrict__ A, int lda, const float* __restrict__ W, int ldw,
    const float* __restrict__ bias, float* __restrict__ C, size_t ldcr, int ldcc,
    int M, int N, int kbeg, int kend, int act)
{
    __shared__ __align__(16) char smem[4 * PARTB];
    uint32_t sb = smem_u32(smem);
    int tid = threadIdx.x;                  // 128
    int lane = tid & 31, wid = tid >> 5;
    int wm = wid >> 1, wn = wid & 1;
    int bm = blockIdx.y * 64, bn = blockIdx.x * 64;

    float acc[2][4][4] = {};

    uint32_t a_off = ((uint32_t)(wm * 32 + (lane & 15)) * LDSE + ((lane & 16) >> 1)) * 2;
    uint32_t b_off = ((uint32_t)(wn * 32 + (lane & 7) + ((lane & 16) >> 1)) * LDSE) * 2
                     + (lane & 8) * 2;

    for (int k0 = kbeg; k0 < kend; k0 += BK) {
        stage_split(A, lda, bm, M, k0, sb, sb + PARTB, tid);
        stage_split(W, ldw, bn, N, k0, sb + 2 * PARTB, sb + 3 * PARTB, tid);
        __syncthreads();
        #pragma unroll
        for (int ks = 0; ks < 2; ks++) {
            uint32_t a_hi[2][4], a_lo[2][4], b_hi[4][2], b_lo[4][2];
            #pragma unroll
            for (int tm = 0; tm < 2; tm++) {
                uint32_t ad = sb + a_off + (uint32_t)tm * 16 * LDSE * 2 + ks * 32;
                ldsm_x4(a_hi[tm][0], a_hi[tm][1], a_hi[tm][2], a_hi[tm][3], ad);
                ldsm_x4(a_lo[tm][0], a_lo[tm][1], a_lo[tm][2], a_lo[tm][3], ad + PARTB);
            }
            #pragma unroll
            for (int tp = 0; tp < 2; tp++) {
                uint32_t bd = sb + 2 * PARTB + b_off
                            + (uint32_t)tp * 16 * LDSE * 2 + ks * 32;
                ldsm_x4(b_hi[2*tp][0], b_hi[2*tp][1], b_hi[2*tp+1][0], b_hi[2*tp+1][1], bd);
                ldsm_x4(b_lo[2*tp][0], b_lo[2*tp][1], b_lo[2*tp+1][0], b_lo[2*tp+1][1],
                        bd + PARTB);
            }
            #pragma unroll
            for (int tm = 0; tm < 2; tm++)
                #pragma unroll
                for (int tn = 0; tn < 4; tn++) {
                    mma_bf16(acc[tm][tn], a_hi[tm], b_hi[tn]);
                    mma_bf16(acc[tm][tn], a_hi[tm], b_lo[tn]);
                    mma_bf16(acc[tm][tn], a_lo[tm], b_hi[tn]);
                }
        }
        __syncthreads();
    }

    int mrow = bm + wm * 32 + (lane >> 2);
    int ncol = bn + wn * 32 + (lane & 3) * 2;
    #pragma unroll
    for (int tm = 0; tm < 2; tm++) {
        #pragma unroll
        for (int half = 0; half < 2; half++) {
            int m = mrow + tm * 16 + half * 8;
            if (m >= M) continue;
            size_t rb = (size_t)m * ldcr;
            #pragma unroll
            for (int tn = 0; tn < 4; tn++) {
                int n = ncol + tn * 8;
                float v0 = acc[tm][tn][half * 2 + 0];
                float v1 = acc[tm][tn][half * 2 + 1];
                if (bias) { v0 += bias[n]; v1 += bias[n + 1]; }
                if (act) { v0 = fmaxf(v0, 0.f); v1 = fmaxf(v1, 0.f); }
                if (ldcc == 1 && n + 1 < N) {
                    *(float2*)(C + rb + n) = make_float2(v0, v1);
                } else {
                    if (n < N)     C[rb + (size_t)n * ldcc]       = v0;
                    if (n + 1 < N) C[rb + (size_t)(n + 1) * ldcc] = v1;
                }
            }
        }
    }
}

__global__ void __launch_bounds__(128) gemm_tc(
    const float* A, const float* W, const float* bias, float* C,
    int M, int N, int K, int act)
{
    gemm_mma_body(A, K, W, K, bias, C, N, 1, M, N, 0, K, act);
}

__global__ void __launch_bounds__(128) gemm_tc_splitk(
    const float* A, const float* W, float* part, int M, int N, int K, int KS)
{
    int chunk = K / KS;
    int z = blockIdx.z;
    gemm_mma_body(A, K, W, K, nullptr, part + (size_t)z * M * N, N, 1,
                  M, N, z * chunk, (z + 1) * chunk, 0);
}

__global__ void __launch_bounds__(128) gemm_tc4(
    const float* A, const float* W0, const float* W1,
    const float* W2, const float* W3, float* C, int M, int N, int K)
{
    int z = blockIdx.z;
    const float* W = (z == 0) ? W0 : (z == 1) ? W1 : (z == 2) ? W2 : W3;
    gemm_mma_body(A, K, W, K, nullptr, C + (size_t)z * M * N, N, 1, M, N, 0, K, 0);
}

// qk[b,h,i,j] = q_{b,i,h,:} . k_{b,j,h,:}   grid (2,2,32)
__global__ void __launch_bounds__(128) gemm_qk(
    const float* __restrict__ q, const float* __restrict__ k, float* __restrict__ qk)
{
    int z = blockIdx.z, b = z >> 3, h = z & 7;
    gemm_mma_body(q + (size_t)b * Ssz * Esz + h * HDsz, Esz,
                  k + (size_t)b * Ssz * Esz + h * HDsz, Esz,
                  nullptr, qk + (size_t)z * Ssz * Ssz, Ssz, 1,
                  Ssz, Ssz, 0, HDsz, 0);
}

// qkp[b,i,r,h] = q_{b,i,h,:} . kproj_{r,h,:}   grid (16,2,32)
__global__ void __launch_bounds__(128) gemm_qkp(
    const float* __restrict__ q, const float* __restrict__ kproj, float* __restrict__ qkp)
{
    int z = blockIdx.z, b = z >> 3, h = z & 7;
    gemm_mma_body(q + (size_t)b * Ssz * Esz + h * HDsz, Esz,
                  kproj + h * HDsz, Esz,
                  nullptr, qkp + (size_t)b * Ssz * 8000 + h, 8000, 8,
                  Ssz, 1000, 0, HDsz, 0);
}

// deterministic split-K reduce (+bias, +relu)
__global__ void reduce_kernel(const float* __restrict__ part, const float* __restrict__ bias,
                              float* __restrict__ C, int MN, int N, int KS, int act)
{
    int i = (blockIdx.x * 256 + threadIdx.x) * 4;
    if (i >= MN) return;
    float4 s = *(const float4*)(part + i);
    for (int z = 1; z < KS; z++) {
        float4 t = *(const float4*)(part + (size_t)z * MN + i);
        s.x += t.x; s.y += t.y; s.z += t.z; s.w += t.w;
    }
    if (bias) {
        int n = i % N;
        s.x += bias[n]; s.y += bias[n + 1]; s.z += bias[n + 2]; s.w += bias[n + 3];
    }
    if (act) {
        s.x = fmaxf(s.x, 0.f); s.y = fmaxf(s.y, 0.f);
        s.z = fmaxf(s.z, 0.f); s.w = fmaxf(s.w, 0.f);
    }
    *(float4*)(C + i) = s;
}

// ======== scores: gather + softmax + mask-split + pos-histogram =============
// block = (i, b), 256 threads
__global__ void scores_kernel(const float* __restrict__ qk, const float* __restrict__ qkp,
                              const float* __restrict__ q,
                              const int* __restrict__ know_adj,
                              const int* __restrict__ pos_mask,
                              const int* __restrict__ adj,
                              const int* __restrict__ smk, const int* __restrict__ omk,
                              const float* __restrict__ pe_k,
                              float* __restrict__ A1, float* __restrict__ A2,
                              float* __restrict__ attn_pos)
{
    int i = blockIdx.x, b = blockIdx.y;
    int tid = threadIdx.x;                  // 0..255
    __shared__ float q_sh[512];
    __shared__ float qk_sh[8 * 128];        // later reused for attn
    __shared__ float qkp_sh[128 * 9];
    __shared__ float qr[8 * 11];
    __shared__ int   ka_sh[128];
    __shared__ int   p_sh[128];

    q_sh[tid]       = q[(size_t)(b * Ssz + i) * Esz + tid];
    q_sh[tid + 256] = q[(size_t)(b * Ssz + i) * Esz + tid + 256];
    if (tid < 128) {
        int ka = know_adj[(size_t)(b * Ssz + i) * Ssz + tid];
        ka_sh[tid] = min(max(ka, 0), 999);
        int p = pos_mask[i * Ssz + tid];
        p_sh[tid] = min(max(p, 0), 10);
    }
    {   // qk load: 1024 floats
        int h = tid >> 5, j4 = (tid & 31) * 4;
        float4 v = *(const float4*)(qk + ((size_t)(b * Hn + h) * Ssz + i) * Ssz + j4);
        *(float4*)(qk_sh + h * 128 + j4) = v;
    }
    __syncthreads();

    {   // qkp gather: 128 rows x 8 heads (two float4 per row)
        int j = tid >> 1, half = tid & 1;
        float4 g = *(const float4*)(qkp + (size_t)(b * Ssz + i) * 8000
                                    + ka_sh[j] * 8 + half * 4);
        float* dst = qkp_sh + j * 9 + half * 4;
        dst[0] = g.x; dst[1] = g.y; dst[2] = g.z; dst[3] = g.w;
    }
    if (tid < 88) {   // qr[h][p] = q_h . pe_k[p]
        int h = tid / 11, p = tid % 11;
        float s = 0.f;
        const float4* pk = (const float4*)(pe_k + p * HDsz);
        const float4* qv = (const float4*)(q_sh + h * 64);
        #pragma unroll
        for (int v = 0; v < 16; v++) {
            float4 e = pk[v], qq = qv[v];
            s += qq.x * e.x + qq.y * e.y + qq.z * e.z + qq.w * e.w;
        }
        qr[h * 11 + p] = s;
    }
    __syncthreads();

    {   // softmax: warp w = head w; lane covers j = l, l+32, l+64, l+96
        int w = tid >> 5, l = tid & 31;
        float s[4];
        float m = -3.4e38f;
        #pragma unroll
        for (int t = 0; t < 4; t++) {
            int j = l + 32 * t;
            float ss = (qk_sh[w * 128 + j] + qkp_sh[j * 9 + w]
                        + qr[w * 11 + p_sh[j]]) * 0.125f;
            if (adj[(size_t)(b * Ssz + i) * Ssz + j] == 0) ss -= 1e30f;
            s[t] = ss;
            m = fmaxf(m, ss);
        }
        #pragma unroll
        for (int o = 16; o; o >>= 1) m = fmaxf(m, __shfl_xor_sync(0xffffffffu, m, o));
        float sum = 0.f;
        float e[4];
        #pragma unroll
        for (int t = 0; t < 4; t++) { e[t] = __expf(s[t] - m); sum += e[t]; }
        #pragma unroll
        for (int o = 16; o; o >>= 1) sum += __shfl_xor_sync(0xffffffffu, sum, o);
        float inv = 1.f / sum;
        size_t rbase = ((size_t)(b * Hn + w) * Ssz + i) * Ssz;
        #pragma unroll
        for (int t = 0; t < 4; t++) {
            int j = l + 32 * t;
            float attn = e[t] * inv;
            A1[rbase + j] = attn * (float)smk[(size_t)(b * Ssz + i) * Ssz + j];
            A2[rbase + j] = attn * (float)omk[(size_t)(b * Ssz + i) * Ssz + j];
            qk_sh[w * 128 + j] = attn;
        }
    }
    __syncthreads();

    if (tid < 88) {   // deterministic position histogram
        int h = tid / 11, p = tid % 11;
        float s = 0.f;
        for (int j = 0; j < 128; j++)
            if (p_sh[j] == p) s += qk_sh[h * 128 + j];
        attn_pos[((size_t)(b * Hn + h) * Ssz + i) * 11 + p] = s;
    }
}

// ================= attention value sum ======================================
__global__ void attnsum_kernel(const float* __restrict__ vs, const float* __restrict__ vo,
                               const float* __restrict__ A1, const float* __restrict__ A2,
                               const float* __restrict__ attn_pos,
                               const float* __restrict__ pe_v,
                               float* __restrict__ outbuf)
{
    int itile = blockIdx.x, hh = blockIdx.y, b = blockIdx.z;
    int tid = threadIdx.x;
    int grp = tid >> 6, d = tid & 63;
    __shared__ float vsh[128 * 65];

    for (int idx = tid; idx < 128 * 64; idx += 256) {
        int j = idx >> 6, dd = idx & 63;
        vsh[j * 65 + dd] = vs[(size_t)(b * Ssz + j) * Esz + hh * HDsz + dd];
    }
    __syncthreads();

    float acc[8];
    #pragma unroll
    for (int it = 0; it < 8; it++) {
        int i = itile * 32 + it * 4 + grp;
        const float* a1 = A1 + ((size_t)(b * Hn + hh) * Ssz + i) * Ssz;
        float s = 0.f;
        #pragma unroll 4
        for (int jj = 0; jj < 128; jj++) s += a1[jj] * vsh[jj * 65 + d];
        acc[it] = s;
    }
    __syncthreads();
    for (int idx = tid; idx < 128 * 64; idx += 256) {
        int j = idx >> 6, dd = idx & 63;
        vsh[j * 65 + dd] = vo[(size_t)(b * Ssz + j) * Esz + hh * HDsz + dd];
    }
    __syncthreads();
    #pragma unroll
    for (int it = 0; it < 8; it++) {
        int i = itile * 32 + it * 4 + grp;
        const float* a2 = A2 + ((size_t)(b * Hn + hh) * Ssz + i) * Ssz;
        float s = acc[it];
        #pragma unroll 4
        for (int jj = 0; jj < 128; jj++) s += a2[jj] * vsh[jj * 65 + d];
        const float* app = attn_pos + ((size_t)(b * Hn + hh) * Ssz + i) * 11;
        #pragma unroll
        for (int p = 0; p < 11; p++) s += app[p] * pe_v[p * HDsz + d];
        outbuf[(size_t)(b * Ssz + i) * Esz + hh * HDsz + d] = s;
    }
}

// ============== residual + layernorm ========================================
__global__ void ln_kernel(const float* __restrict__ x, const float* __restrict__ dlt,
                          const float* __restrict__ g, const float* __restrict__ bt,
                          float* __restrict__ dst)
{
    int row = blockIdx.x;
    int tid = threadIdx.x;   // 256
    __shared__ float red[8];
    const float* xr = x + (size_t)row * Esz;
    const float* dr = dlt + (size_t)row * Esz;
    float v0 = xr[tid] + dr[tid];
    float v1 = xr[tid + 256] + dr[tid + 256];
    float s = v0 + v1;
    #pragma unroll
    for (int o = 16; o; o >>= 1) s += __shfl_xor_sync(0xffffffffu, s, o);
    if ((tid & 31) == 0) red[tid >> 5] = s;
    __syncthreads();
    float mean = 0.f;
    #pragma unroll
    for (int w = 0; w < 8; w++) mean += red[w];
    mean *= (1.f / 512.f);
    __syncthreads();
    float e0 = v0 - mean, e1 = v1 - mean;
    float s2 = e0 * e0 + e1 * e1;
    #pragma unroll
    for (int o = 16; o; o >>= 1) s2 += __shfl_xor_sync(0xffffffffu, s2, o);
    if ((tid & 31) == 0) red[tid >> 5] = s2;
    __syncthreads();
    float var = 0.f;
    #pragma unroll
    for (int w = 0; w < 8; w++) var += red[w];
    var *= (1.f / 512.f);
    float rstd = rsqrtf(var + 1e-5f);
    dst[(size_t)row * Esz + tid]       = e0 * rstd * g[tid] + bt[tid];
    dst[(size_t)row * Esz + 256 + tid] = e1 * rstd * g[tid + 256] + bt[tid + 256];
}

__global__ void copy_kernel(float* __restrict__ dst, const float* __restrict__ src, int n)
{
    int i = blockIdx.x * blockDim.x + threadIdx.x;
    if (i < n) dst[i] = src[i];
}

// ===================== host orchestration ===================================
extern "C" void kernel_launch(void* const* d_in, const int* in_sizes, int n_in,
                              void* d_out, int out_size)
{
    const float* x        = (const float*)d_in[0];
    const int*   adj      = (const int*)d_in[1];
    const int*   smk      = (const int*)d_in[2];
    const int*   omk      = (const int*)d_in[3];
    const float* knowledge= (const float*)d_in[4];
    const int*   know_adj = (const int*)d_in[5];
    const int*   pos_mask = (const int*)d_in[6];
    const float* pe_k     = (const float*)d_in[7];
    const float* pe_v     = (const float*)d_in[8];
    const float* Wq       = (const float*)d_in[9];
    const float* Wk       = (const float*)d_in[10];
    const float* Wvs      = (const float*)d_in[11];
    const float* Wvo      = (const float*)d_in[12];
    const float* Wo       = (const float*)d_in[13];
    const float* Wkn      = (const float*)d_in[14];
    const float* ln1g     = (const float*)d_in[15];
    const float* ln1b     = (const float*)d_in[16];
    const float* w1       = (const float*)d_in[17];
    const float* b1       = (const float*)d_in[18];
    const float* w2       = (const float*)d_in[19];
    const float* b2       = (const float*)d_in[20];
    const float* ln2g     = (const float*)d_in[21];
    const float* ln2b     = (const float*)d_in[22];
    float* out = (float*)d_out;

    float *h, *qkv, *kproj, *A1, *A2, *ap, *asum, *tmp, *ff, *part, *qkp;
    cudaGetSymbolAddress((void**)&h, g_h);
    cudaGetSymbolAddress((void**)&qkv, g_qkv);
    cudaGetSymbolAddress((void**)&kproj, g_kproj);
    cudaGetSymbolAddress((void**)&A1, g_A1);
    cudaGetSymbolAddress((void**)&A2, g_A2);
    cudaGetSymbolAddress((void**)&ap, g_ap);
    cudaGetSymbolAddress((void**)&asum, g_attnsum);
    cudaGetSymbolAddress((void**)&tmp, g_tmp);
    cudaGetSymbolAddress((void**)&ff, g_ff);
    cudaGetSymbolAddress((void**)&part, g_part);
    cudaGetSymbolAddress((void**)&qkp, g_qkp);

    copy_kernel<<<(Msz * Esz + 255) / 256, 256>>>(h, x, Msz * Esz);

    const size_t EE = (size_t)Esz * Esz;
    const size_t FE = (size_t)FFsz * Esz;
    for (int l = 0; l < Lnum; l++) {
        const float* wq  = Wq  + (size_t)l * EE;
        const float* wk  = Wk  + (size_t)l * EE;
        const float* wvs = Wvs + (size_t)l * EE;
        const float* wvo = Wvo + (size_t)l * EE;
        const float* wo  = Wo  + (size_t)l * EE;
        const float* wkn = Wkn + (size_t)l * EE;

        // q,k,vs,vo projections (256 CTAs)
        gemm_tc4<<<dim3(8, 8, 4), 128>>>(h, wq, wk, wvs, wvo, qkv, Msz, Esz, Esz);
        // knowledge projection table [1000, 512] (128 CTAs)
        gemm_tc<<<dim3(8, 16), 128>>>(knowledge, wkn, nullptr, kproj, 1000, Esz, Esz, 0);
        // qk[b,h,i,j] (128 CTAs) -> reuse part buffer (2 MB)
        gemm_qk<<<dim3(2, 2, 32), 128>>>(qkv, qkv + (size_t)Msz * Esz, part);
        // qkp[b,i,r,h] (1024 CTAs)
        gemm_qkp<<<dim3(16, 2, 32), 128>>>(qkv, kproj, qkp);
        // scores: gather + softmax + mask-split + pos histogram
        scores_kernel<<<dim3(Ssz, Bsz), 256>>>(
            part, qkp, qkv, know_adj, pos_mask, adj, smk, omk,
            pe_k, A1, A2, ap);
        // attention value sum
        attnsum_kernel<<<dim3(4, Hn, Bsz), 256>>>(
            qkv + 2 * (size_t)Msz * Esz, qkv + 3 * (size_t)Msz * Esz,
            A1, A2, ap, pe_v, asum);
        // output projection, split-K=2 (128 CTAs)
        gemm_tc_splitk<<<dim3(8, 8, 2), 128>>>(asum, wo, part, Msz, Esz, Esz, 2);
        reduce_kernel<<<(Msz * Esz / 4 + 255) / 256, 256>>>(part, nullptr, tmp,
                                                            Msz * Esz, Esz, 2, 0);
        // residual + LN1
        ln_kernel<<<Msz, 256>>>(h, tmp, ln1g + l * Esz, ln1b + l * Esz, h);
        // FFN1 (256 CTAs, fused bias+relu)
        gemm_tc<<<dim3(32, 8), 128>>>(h, w1 + (size_t)l * FE, b1 + (size_t)l * FFsz,
                                      ff, Msz, FFsz, Esz, 1);
        // FFN2, split-K=4 (256 CTAs)
        gemm_tc_splitk<<<dim3(8, 8, 4), 128>>>(ff, w2 + (size_t)l * FE, part,
                                               Msz, Esz, FFsz, 4);
        reduce_kernel<<<(Msz * Esz / 4 + 255) / 256, 256>>>(part, b2 + l * Esz, tmp,
                                                            Msz * Esz, Esz, 4, 0);
        // residual + LN2 (final layer -> d_out)
        float* dst = (l == Lnum - 1) ? out : h;
        ln_kernel<<<Msz, 256>>>(h, tmp, ln2g + l * Esz, ln2b + l * Esz, dst);
    }
}

// round 8
// speedup vs baseline: 1.8758x; 1.1194x over previous
#include <cuda_runtime.h>
#include <cuda_bf16.h>
#include <cstdint>

#define Bsz 4
#define Ssz 128
#define Esz 512
#define Hn 8
#define HDsz 64
#define FFsz 2048
#define Lnum 4
#define Msz (Bsz*Ssz)   /* 512 rows */

// ===================== scratch (static device memory) ======================
__device__ float g_h[Msz*Esz];
__device__ float g_qkv[4*Msz*Esz];
__device__ float g_kproj[1024*Esz];
__device__ float g_A1[Bsz*Hn*Ssz*Ssz];
__device__ float g_A2[Bsz*Hn*Ssz*Ssz];
__device__ float g_ap[Bsz*Hn*Ssz*11];
__device__ float g_attnsum[Msz*Esz];
__device__ float g_ff[Msz*FFsz];
__device__ float g_part[4*512*512];     // split-K partials / qk buffer
__device__ float g_qk[Bsz*Hn*Ssz*Ssz];
__device__ float g_qkp[512*8000];       // qkp[b,i,r,h]  (16 MB)

// ===================== helpers ==============================================
__device__ __forceinline__ void split1(float x, unsigned short& h, unsigned short& l)
{
    __nv_bfloat16 hb = __float2bfloat16(x);
    h = __bfloat16_as_ushort(hb);
    l = __bfloat16_as_ushort(__float2bfloat16(x - __bfloat162float(hb)));
}
__device__ __forceinline__ void ldsm_x4(uint32_t& r0, uint32_t& r1,
                                        uint32_t& r2, uint32_t& r3, uint32_t addr)
{
    asm volatile("ldmatrix.sync.aligned.m8n8.x4.shared.b16 {%0,%1,%2,%3}, [%4];"
                 : "=r"(r0), "=r"(r1), "=r"(r2), "=r"(r3) : "r"(addr));
}
__device__ __forceinline__ void mma_bf16(float* c, const uint32_t* a, const uint32_t* b)
{
    asm volatile("mma.sync.aligned.m16n8k16.row.col.f32.bf16.bf16.f32 "
                 "{%0,%1,%2,%3},{%4,%5,%6,%7},{%8,%9},{%0,%1,%2,%3};"
                 : "+f"(c[0]), "+f"(c[1]), "+f"(c[2]), "+f"(c[3])
                 : "r"(a[0]), "r"(a[1]), "r"(a[2]), "r"(a[3]), "r"(b[0]), "r"(b[1]));
}
__device__ __forceinline__ uint32_t smem_u32(const void* p) {
    uint32_t a;
    asm("{ .reg .u64 t; cvta.to.shared.u64 t, %1; cvt.u32.u64 %0, t; }" : "=r"(a) : "l"(p));
    return a;
}

// ===================== tensor-core bf16x3 GEMM ==============================
// C[m,n] = sum_k A[m,k] * W[n,k] over [kbeg,kend). Reg-double-buffered staging.
// 64x64 CTA tile, 128 threads (2m x 2n warps, warp tile 32x32), BK=32.
#define BK 32
#define LDSE 40                 /* bf16 elems per smem row (80 B) */
#define PARTB (64*LDSE*2)       /* 5120 B per matrix part */

// load this thread's 32B x 2 slice of next chunk into registers
__device__ __forceinline__ void load_chunk(
    const float* __restrict__ A, int lda, int row0a, int Ma,
    const float* __restrict__ W, int ldw, int row0w, int Nw,
    int k0, int tid, float4* ra, float4* rw)
{
    int r = tid >> 1, half = tid & 1;
    int ga = min(row0a + r, Ma - 1);
    int gw = min(row0w + r, Nw - 1);
    const float4* pa = (const float4*)(A + (size_t)ga * lda + k0 + half * 16);
    const float4* pw = (const float4*)(W + (size_t)gw * ldw + k0 + half * 16);
    #pragma unroll
    for (int u = 0; u < 4; u++) { ra[u] = pa[u]; rw[u] = pw[u]; }
}

// split regs -> smem hi/lo bf16
__device__ __forceinline__ void store_chunk(uint32_t s_hi, uint32_t s_lo,
                                            const float4* rv, int tid)
{
    int r = tid >> 1, half = tid & 1;
    uint32_t off = (uint32_t)r * (LDSE * 2) + half * 32;
    #pragma unroll
    for (int u = 0; u < 4; u++) {
        float4 v = rv[u];
        ushort4 hh, ll;
        split1(v.x, hh.x, ll.x); split1(v.y, hh.y, ll.y);
        split1(v.z, hh.z, ll.z); split1(v.w, hh.w, ll.w);
        asm volatile("st.shared.v4.u16 [%0], {%1,%2,%3,%4};"
                     :: "r"(s_hi + off + u * 8), "h"(hh.x), "h"(hh.y), "h"(hh.z), "h"(hh.w));
        asm volatile("st.shared.v4.u16 [%0], {%1,%2,%3,%4};"
                     :: "r"(s_lo + off + u * 8), "h"(ll.x), "h"(ll.y), "h"(ll.z), "h"(ll.w));
    }
}

__device__ __forceinline__ void gemm_mma_body(
    const float* __restrict__ A, int lda, const float* __restrict__ W, int ldw,
    const float* __restrict__ bias, float* __restrict__ C, size_t ldcr, int ldcc,
    int bm, int bn, int M, int N, int kbeg, int kend, int act)
{
    __shared__ __align__(16) char smem[4 * PARTB];
    uint32_t sb = smem_u32(smem);
    int tid = threadIdx.x;                  // 128
    int lane = tid & 31, wid = tid >> 5;
    int wm = wid >> 1, wn = wid & 1;

    float acc[2][4][4] = {};

    uint32_t a_off = ((uint32_t)(wm * 32 + (lane & 15)) * LDSE + ((lane & 16) >> 1)) * 2;
    uint32_t b_off = ((uint32_t)(wn * 32 + (lane & 7) + ((lane & 16) >> 1)) * LDSE) * 2
                     + (lane & 8) * 2;

    float4 ra[4], rw[4];
    load_chunk(A, lda, bm, M, W, ldw, bn, N, kbeg, tid, ra, rw);

    for (int k0 = kbeg; k0 < kend; k0 += BK) {
        store_chunk(sb, sb + PARTB, ra, tid);
        store_chunk(sb + 2 * PARTB, sb + 3 * PARTB, rw, tid);
        __syncthreads();
        if (k0 + BK < kend)
            load_chunk(A, lda, bm, M, W, ldw, bn, N, k0 + BK, tid, ra, rw);
        #pragma unroll
        for (int ks = 0; ks < 2; ks++) {
            uint32_t a_hi[2][4], a_lo[2][4], b_hi[4][2], b_lo[4][2];
            #pragma unroll
            for (int tm = 0; tm < 2; tm++) {
                uint32_t ad = sb + a_off + (uint32_t)tm * 16 * LDSE * 2 + ks * 32;
                ldsm_x4(a_hi[tm][0], a_hi[tm][1], a_hi[tm][2], a_hi[tm][3], ad);
                ldsm_x4(a_lo[tm][0], a_lo[tm][1], a_lo[tm][2], a_lo[tm][3], ad + PARTB);
            }
            #pragma unroll
            for (int tp = 0; tp < 2; tp++) {
                uint32_t bd = sb + 2 * PARTB + b_off
                            + (uint32_t)tp * 16 * LDSE * 2 + ks * 32;
                ldsm_x4(b_hi[2*tp][0], b_hi[2*tp][1], b_hi[2*tp+1][0], b_hi[2*tp+1][1], bd);
                ldsm_x4(b_lo[2*tp][0], b_lo[2*tp][1], b_lo[2*tp+1][0], b_lo[2*tp+1][1],
                        bd + PARTB);
            }
            #pragma unroll
            for (int tm = 0; tm < 2; tm++)
                #pragma unroll
                for (int tn = 0; tn < 4; tn++) {
                    mma_bf16(acc[tm][tn], a_hi[tm], b_hi[tn]);
                    mma_bf16(acc[tm][tn], a_hi[tm], b_lo[tn]);
                    mma_bf16(acc[tm][tn], a_lo[tm], b_hi[tn]);
                }
        }
        __syncthreads();
    }

    int mrow = bm + wm * 32 + (lane >> 2);
    int ncol = bn + wn * 32 + (lane & 3) * 2;
    #pragma unroll
    for (int tm = 0; tm < 2; tm++) {
        #pragma unroll
        for (int half = 0; half < 2; half++) {
            int m = mrow + tm * 16 + half * 8;
            if (m >= M) continue;
            size_t rb = (size_t)m * ldcr;
            #pragma unroll
            for (int tn = 0; tn < 4; tn++) {
                int n = ncol + tn * 8;
                float v0 = acc[tm][tn][half * 2 + 0];
                float v1 = acc[tm][tn][half * 2 + 1];
                if (bias) { v0 += bias[n]; v1 += bias[n + 1]; }
                if (act) { v0 = fmaxf(v0, 0.f); v1 = fmaxf(v1, 0.f); }
                if (ldcc == 1 && n + 1 < N) {
                    *(float2*)(C + rb + n) = make_float2(v0, v1);
                } else {
                    if (n < N)     C[rb + (size_t)n * ldcc]       = v0;
                    if (n + 1 < N) C[rb + (size_t)(n + 1) * ldcc] = v1;
                }
            }
        }
    }
}

__global__ void __launch_bounds__(128) gemm_tc(
    const float* A, const float* W, const float* bias, float* C,
    int M, int N, int K, int act)
{
    gemm_mma_body(A, K, W, K, bias, C, N, 1,
                  blockIdx.y * 64, blockIdx.x * 64, M, N, 0, K, act);
}

__global__ void __launch_bounds__(128) gemm_tc_splitk(
    const float* A, const float* W, float* part, int M, int N, int K, int KS)
{
    int chunk = K / KS;
    int z = blockIdx.z;
    gemm_mma_body(A, K, W, K, nullptr, part + (size_t)z * M * N, N, 1,
                  blockIdx.y * 64, blockIdx.x * 64, M, N, z * chunk, (z + 1) * chunk, 0);
}

__global__ void __launch_bounds__(128) gemm_tc4(
    const float* A, const float* W0, const float* W1,
    const float* W2, const float* W3, float* C, int M, int N, int K)
{
    int z = blockIdx.z;
    const float* W = (z == 0) ? W0 : (z == 1) ? W1 : (z == 2) ? W2 : W3;
    gemm_mma_body(A, K, W, K, nullptr, C + (size_t)z * M * N, N, 1,
                  blockIdx.y * 64, blockIdx.x * 64, M, N, 0, K, 0);
}

// combined qk + qkp: grid (18, 2, 32)
//   x in [0,16): qkp[b,i,r,h] tiles (N=1000, strided out)
//   x in [16,18): qk[b,h,i,j] tiles (N=128)
__global__ void __launch_bounds__(128) gemm_qkqkp(
    const float* __restrict__ q, const float* __restrict__ k,
    const float* __restrict__ kproj,
    float* __restrict__ qk, float* __restrict__ qkp)
{
    int z = blockIdx.z, b = z >> 3, h = z & 7;
    const float* qa = q + (size_t)b * Ssz * Esz + h * HDsz;
    int bm = blockIdx.y * 64;
    if (blockIdx.x < 16) {
        gemm_mma_body(qa, Esz, kproj + h * HDsz, Esz, nullptr,
                      qkp + (size_t)b * Ssz * 8000 + h, 8000, 8,
                      bm, blockIdx.x * 64, Ssz, 1000, 0, HDsz, 0);
    } else {
        gemm_mma_body(qa, Esz, k + (size_t)b * Ssz * Esz + h * HDsz, Esz, nullptr,
                      qk + (size_t)z * Ssz * Ssz, Ssz, 1,
                      bm, (blockIdx.x - 16) * 64, Ssz, Ssz, 0, HDsz, 0);
    }
}

// ======== scores: gather + softmax + mask-split + pos-histogram =============
__global__ void scores_kernel(const float* __restrict__ qk, const float* __restrict__ qkp,
                              const float* __restrict__ q,
                              const int* __restrict__ know_adj,
                              const int* __restrict__ pos_mask,
                              const int* __restrict__ adj,
                              const int* __restrict__ smk, const int* __restrict__ omk,
                              const float* __restrict__ pe_k,
                              float* __restrict__ A1, float* __restrict__ A2,
                              float* __restrict__ attn_pos)
{
    int i = blockIdx.x, b = blockIdx.y;
    int tid = threadIdx.x;                  // 0..255
    __shared__ float q_sh[512];
    __shared__ float qk_sh[8 * 128];        // later reused for attn
    __shared__ float qkp_sh[128 * 9];
    __shared__ float qr[8 * 11];
    __shared__ int   ka_sh[128];
    __shared__ int   p_sh[128];

    q_sh[tid]       = q[(size_t)(b * Ssz + i) * Esz + tid];
    q_sh[tid + 256] = q[(size_t)(b * Ssz + i) * Esz + tid + 256];
    if (tid < 128) {
        int ka = know_adj[(size_t)(b * Ssz + i) * Ssz + tid];
        ka_sh[tid] = min(max(ka, 0), 999);
        int p = pos_mask[i * Ssz + tid];
        p_sh[tid] = min(max(p, 0), 10);
    }
    {
        int h = tid >> 5, j4 = (tid & 31) * 4;
        float4 v = *(const float4*)(qk + ((size_t)(b * Hn + h) * Ssz + i) * Ssz + j4);
        *(float4*)(qk_sh + h * 128 + j4) = v;
    }
    __syncthreads();

    {
        int j = tid >> 1, half = tid & 1;
        float4 g = *(const float4*)(qkp + (size_t)(b * Ssz + i) * 8000
                                    + ka_sh[j] * 8 + half * 4);
        float* dst = qkp_sh + j * 9 + half * 4;
        dst[0] = g.x; dst[1] = g.y; dst[2] = g.z; dst[3] = g.w;
    }
    if (tid < 88) {
        int h = tid / 11, p = tid % 11;
        float s = 0.f;
        const float4* pk = (const float4*)(pe_k + p * HDsz);
        const float4* qv = (const float4*)(q_sh + h * 64);
        #pragma unroll
        for (int v = 0; v < 16; v++) {
            float4 e = pk[v], qq = qv[v];
            s += qq.x * e.x + qq.y * e.y + qq.z * e.z + qq.w * e.w;
        }
        qr[h * 11 + p] = s;
    }
    __syncthreads();

    {
        int w = tid >> 5, l = tid & 31;
        float s[4];
        float m = -3.4e38f;
        #pragma unroll
        for (int t = 0; t < 4; t++) {
            int j = l + 32 * t;
            float ss = (qk_sh[w * 128 + j] + qkp_sh[j * 9 + w]
                        + qr[w * 11 + p_sh[j]]) * 0.125f;
            if (adj[(size_t)(b * Ssz + i) * Ssz + j] == 0) ss -= 1e30f;
            s[t] = ss;
            m = fmaxf(m, ss);
        }
        #pragma unroll
        for (int o = 16; o; o >>= 1) m = fmaxf(m, __shfl_xor_sync(0xffffffffu, m, o));
        float sum = 0.f;
        float e[4];
        #pragma unroll
        for (int t = 0; t < 4; t++) { e[t] = __expf(s[t] - m); sum += e[t]; }
        #pragma unroll
        for (int o = 16; o; o >>= 1) sum += __shfl_xor_sync(0xffffffffu, sum, o);
        float inv = 1.f / sum;
        size_t rbase = ((size_t)(b * Hn + w) * Ssz + i) * Ssz;
        #pragma unroll
        for (int t = 0; t < 4; t++) {
            int j = l + 32 * t;
            float attn = e[t] * inv;
            A1[rbase + j] = attn * (float)smk[(size_t)(b * Ssz + i) * Ssz + j];
            A2[rbase + j] = attn * (float)omk[(size_t)(b * Ssz + i) * Ssz + j];
            qk_sh[w * 128 + j] = attn;
        }
    }
    __syncthreads();

    if (tid < 88) {
        int h = tid / 11, p = tid % 11;
        float s = 0.f;
        for (int j = 0; j < 128; j++)
            if (p_sh[j] == p) s += qk_sh[h * 128 + j];
        attn_pos[((size_t)(b * Hn + h) * Ssz + i) * 11 + p] = s;
    }
}

// ================= attention value sum ======================================
__global__ void attnsum_kernel(const float* __restrict__ vs, const float* __restrict__ vo,
                               const float* __restrict__ A1, const float* __restrict__ A2,
                               const float* __restrict__ attn_pos,
                               const float* __restrict__ pe_v,
                               float* __restrict__ outbuf)
{
    int itile = blockIdx.x, hh = blockIdx.y, b = blockIdx.z;
    int tid = threadIdx.x;
    int grp = tid >> 6, d = tid & 63;
    __shared__ float vsh[128 * 65];

    for (int idx = tid; idx < 128 * 64; idx += 256) {
        int j = idx >> 6, dd = idx & 63;
        vsh[j * 65 + dd] = vs[(size_t)(b * Ssz + j) * Esz + hh * HDsz + dd];
    }
    __syncthreads();

    float acc[8];
    #pragma unroll
    for (int it = 0; it < 8; it++) {
        int i = itile * 32 + it * 4 + grp;
        const float* a1 = A1 + ((size_t)(b * Hn + hh) * Ssz + i) * Ssz;
        float s = 0.f;
        #pragma unroll 4
        for (int jj = 0; jj < 128; jj++) s += a1[jj] * vsh[jj * 65 + d];
        acc[it] = s;
    }
    __syncthreads();
    for (int idx = tid; idx < 128 * 64; idx += 256) {
        int j = idx >> 6, dd = idx & 63;
        vsh[j * 65 + dd] = vo[(size_t)(b * Ssz + j) * Esz + hh * HDsz + dd];
    }
    __syncthreads();
    #pragma unroll
    for (int it = 0; it < 8; it++) {
        int i = itile * 32 + it * 4 + grp;
        const float* a2 = A2 + ((size_t)(b * Hn + hh) * Ssz + i) * Ssz;
        float s = acc[it];
        #pragma unroll 4
        for (int jj = 0; jj < 128; jj++) s += a2[jj] * vsh[jj * 65 + d];
        const float* app = attn_pos + ((size_t)(b * Hn + hh) * Ssz + i) * 11;
        #pragma unroll
        for (int p = 0; p < 11; p++) s += app[p] * pe_v[p * HDsz + d];
        outbuf[(size_t)(b * Ssz + i) * Esz + hh * HDsz + d] = s;
    }
}

// ===== fused split-K reduce + bias + residual + layernorm ===================
__global__ void ln_red_kernel(const float* __restrict__ x, const float* __restrict__ part,
                              int KS, const float* __restrict__ bias,
                              const float* __restrict__ g, const float* __restrict__ bt,
                              float* __restrict__ dst)
{
    const int MN = Msz * Esz;
    int row = blockIdx.x;
    int tid = threadIdx.x;   // 256
    __shared__ float red[8];
    size_t i0 = (size_t)row * Esz + tid;
    size_t i1 = i0 + 256;
    float v0 = x[i0], v1 = x[i1];
    for (int z = 0; z < KS; z++) {
        v0 += part[(size_t)z * MN + i0];
        v1 += part[(size_t)z * MN + i1];
    }
    if (bias) { v0 += bias[tid]; v1 += bias[tid + 256]; }
    float s = v0 + v1;
    #pragma unroll
    for (int o = 16; o; o >>= 1) s += __shfl_xor_sync(0xffffffffu, s, o);
    if ((tid & 31) == 0) red[tid >> 5] = s;
    __syncthreads();
    float mean = 0.f;
    #pragma unroll
    for (int w = 0; w < 8; w++) mean += red[w];
    mean *= (1.f / 512.f);
    __syncthreads();
    float e0 = v0 - mean, e1 = v1 - mean;
    float s2 = e0 * e0 + e1 * e1;
    #pragma unroll
    for (int o = 16; o; o >>= 1) s2 += __shfl_xor_sync(0xffffffffu, s2, o);
    if ((tid & 31) == 0) red[tid >> 5] = s2;
    __syncthreads();
    float var = 0.f;
    #pragma unroll
    for (int w = 0; w < 8; w++) var += red[w];
    var *= (1.f / 512.f);
    float rstd = rsqrtf(var + 1e-5f);
    dst[i0] = e0 * rstd * g[tid] + bt[tid];
    dst[i1] = e1 * rstd * g[tid + 256] + bt[tid + 256];
}

__global__ void copy_kernel(float* __restrict__ dst, const float* __restrict__ src, int n)
{
    int i = blockIdx.x * blockDim.x + threadIdx.x;
    if (i < n) dst[i] = src[i];
}

// ===================== host orchestration ===================================
extern "C" void kernel_launch(void* const* d_in, const int* in_sizes, int n_in,
                              void* d_out, int out_size)
{
    const float* x        = (const float*)d_in[0];
    const int*   adj      = (const int*)d_in[1];
    const int*   smk      = (const int*)d_in[2];
    const int*   omk      = (const int*)d_in[3];
    const float* knowledge= (const float*)d_in[4];
    const int*   know_adj = (const int*)d_in[5];
    const int*   pos_mask = (const int*)d_in[6];
    const float* pe_k     = (const float*)d_in[7];
    const float* pe_v     = (const float*)d_in[8];
    const float* Wq       = (const float*)d_in[9];
    const float* Wk       = (const float*)d_in[10];
    const float* Wvs      = (const float*)d_in[11];
    const float* Wvo      = (const float*)d_in[12];
    const float* Wo       = (const float*)d_in[13];
    const float* Wkn      = (const float*)d_in[14];
    const float* ln1g     = (const float*)d_in[15];
    const float* ln1b     = (const float*)d_in[16];
    const float* w1       = (const float*)d_in[17];
    const float* b1       = (const float*)d_in[18];
    const float* w2       = (const float*)d_in[19];
    const float* b2       = (const float*)d_in[20];
    const float* ln2g     = (const float*)d_in[21];
    const float* ln2b     = (const float*)d_in[22];
    float* out = (float*)d_out;

    float *h, *qkv, *kproj, *A1, *A2, *ap, *asum, *ff, *part, *qkbuf, *qkp;
    cudaGetSymbolAddress((void**)&h, g_h);
    cudaGetSymbolAddress((void**)&qkv, g_qkv);
    cudaGetSymbolAddress((void**)&kproj, g_kproj);
    cudaGetSymbolAddress((void**)&A1, g_A1);
    cudaGetSymbolAddress((void**)&A2, g_A2);
    cudaGetSymbolAddress((void**)&ap, g_ap);
    cudaGetSymbolAddress((void**)&asum, g_attnsum);
    cudaGetSymbolAddress((void**)&ff, g_ff);
    cudaGetSymbolAddress((void**)&part, g_part);
    cudaGetSymbolAddress((void**)&qkbuf, g_qk);
    cudaGetSymbolAddress((void**)&qkp, g_qkp);

    copy_kernel<<<(Msz * Esz + 255) / 256, 256>>>(h, x, Msz * Esz);

    const size_t EE = (size_t)Esz * Esz;
    const size_t FE = (size_t)FFsz * Esz;
    for (int l = 0; l < Lnum; l++) {
        const float* wq  = Wq  + (size_t)l * EE;
        const float* wk  = Wk  + (size_t)l * EE;
        const float* wvs = Wvs + (size_t)l * EE;
        const float* wvo = Wvo + (size_t)l * EE;
        const float* wo  = Wo  + (size_t)l * EE;
        const float* wkn = Wkn + (size_t)l * EE;

        // q,k,vs,vo projections (256 CTAs)
        gemm_tc4<<<dim3(8, 8, 4), 128>>>(h, wq, wk, wvs, wvo, qkv, Msz, Esz, Esz);
        // knowledge projection table [1000, 512] (128 CTAs)
        gemm_tc<<<dim3(8, 16), 128>>>(knowledge, wkn, nullptr, kproj, 1000, Esz, Esz, 0);
        // qk + qkp in one launch (1152 CTAs)
        gemm_qkqkp<<<dim3(18, 2, 32), 128>>>(qkv, qkv + (size_t)Msz * Esz, kproj,
                                             qkbuf, qkp);
        // scores: gather + softmax + mask-split + pos histogram
        scores_kernel<<<dim3(Ssz, Bsz), 256>>>(
            qkbuf, qkp, qkv, know_adj, pos_mask, adj, smk, omk,
            pe_k, A1, A2, ap);
        // attention value sum
        attnsum_kernel<<<dim3(4, Hn, Bsz), 256>>>(
            qkv + 2 * (size_t)Msz * Esz, qkv + 3 * (size_t)Msz * Esz,
            A1, A2, ap, pe_v, asum);
        // output projection, split-K=2 (128 CTAs) + fused reduce+LN1
        gemm_tc_splitk<<<dim3(8, 8, 2), 128>>>(asum, wo, part, Msz, Esz, Esz, 2);
        ln_red_kernel<<<Msz, 256>>>(h, part, 2, nullptr,
                                    ln1g + l * Esz, ln1b + l * Esz, h);
        // FFN1 (256 CTAs, fused bias+relu)
        gemm_tc<<<dim3(32, 8), 128>>>(h, w1 + (size_t)l * FE, b1 + (size_t)l * FFsz,
                                      ff, Msz, FFsz, Esz, 1);
        // FFN2, split-K=4 (256 CTAs) + fused reduce+bias+LN2
        gemm_tc_splitk<<<dim3(8, 8, 4), 128>>>(ff, w2 + (size_t)l * FE, part,
                                               Msz, Esz, FFsz, 4);
        float* dst = (l == Lnum - 1) ? out : h;
        ln_red_kernel<<<Msz, 256>>>(h, part, 4, b2 + l * Esz,
                                    ln2g + l * Esz, ln2b + l * Esz, dst);
    }
}

// round 9
// speedup vs baseline: 1.9748x; 1.0528x over previous
#include <cuda_runtime.h>
#include <cuda_bf16.h>
#include <cstdint>

#define Bsz 4
#define Ssz 128
#define Esz 512
#define Hn 8
#define HDsz 64
#define FFsz 2048
#define Lnum 4
#define Msz (Bsz*Ssz)   /* 512 rows */

// ===================== scratch (static device memory) ======================
__device__ float g_h[Msz*Esz];
__device__ float g_qkv[4*Msz*Esz];
__device__ float g_kproj[1024*Esz];
__device__ float g_A1[Bsz*Hn*Ssz*Ssz];
__device__ float g_A2[Bsz*Hn*Ssz*Ssz];
__device__ float g_ap[Bsz*Hn*Ssz*11];
__device__ float g_attnsum[Msz*Esz];
__device__ float g_ff[Msz*FFsz];
__device__ float g_part[4*512*512];     // split-K partials
__device__ float g_qk[Bsz*Hn*Ssz*Ssz];
__device__ float g_qkp[512*8000];       // qkp[b,i,r,h]  (16 MB)

// ===================== helpers ==============================================
__device__ __forceinline__ void split1(float x, unsigned short& h, unsigned short& l)
{
    __nv_bfloat16 hb = __float2bfloat16(x);
    h = __bfloat16_as_ushort(hb);
    l = __bfloat16_as_ushort(__float2bfloat16(x - __bfloat162float(hb)));
}
__device__ __forceinline__ void ldsm_x4(uint32_t& r0, uint32_t& r1,
                                        uint32_t& r2, uint32_t& r3, uint32_t addr)
{
    asm volatile("ldmatrix.sync.aligned.m8n8.x4.shared.b16 {%0,%1,%2,%3}, [%4];"
                 : "=r"(r0), "=r"(r1), "=r"(r2), "=r"(r3) : "r"(addr));
}
__device__ __forceinline__ void mma_bf16(float* c, const uint32_t* a, const uint32_t* b)
{
    asm volatile("mma.sync.aligned.m16n8k16.row.col.f32.bf16.bf16.f32 "
                 "{%0,%1,%2,%3},{%4,%5,%6,%7},{%8,%9},{%0,%1,%2,%3};"
                 : "+f"(c[0]), "+f"(c[1]), "+f"(c[2]), "+f"(c[3])
                 : "r"(a[0]), "r"(a[1]), "r"(a[2]), "r"(a[3]), "r"(b[0]), "r"(b[1]));
}
__device__ __forceinline__ uint32_t smem_u32(const void* p) {
    uint32_t a;
    asm("{ .reg .u64 t; cvta.to.shared.u64 t, %1; cvt.u32.u64 %0, t; }" : "=r"(a) : "l"(p));
    return a;
}

// ===================== tensor-core bf16x3 GEMM ==============================
// C[m,n] = sum_k A[m,k] * W[n,k] over [kbeg,kend).
// Reg prefetch + smem double buffer -> ONE sync per K-chunk.
// 64x64 CTA tile, 128 threads (2m x 2n warps, warp tile 32x32), BK=32.
#define BK 32
#define LDSE 40                 /* bf16 elems per smem row (80 B) */
#define PARTB (64*LDSE*2)       /* 5120 B per matrix part */
#define STAGEB (4*PARTB)        /* 20480 B per stage */

__device__ __forceinline__ void load_chunk(
    const float* __restrict__ A, int lda, int row0a, int Ma,
    const float* __restrict__ W, int ldw, int row0w, int Nw,
    int k0, int tid, float4* ra, float4* rw)
{
    int r = tid >> 1, half = tid & 1;
    int ga = min(row0a + r, Ma - 1);
    int gw = min(row0w + r, Nw - 1);
    const float4* pa = (const float4*)(A + (size_t)ga * lda + k0 + half * 16);
    const float4* pw = (const float4*)(W + (size_t)gw * ldw + k0 + half * 16);
    #pragma unroll
    for (int u = 0; u < 4; u++) { ra[u] = pa[u]; rw[u] = pw[u]; }
}

__device__ __forceinline__ void store_chunk(uint32_t s_hi, uint32_t s_lo,
                                            const float4* rv, int tid)
{
    int r = tid >> 1, half = tid & 1;
    uint32_t off = (uint32_t)r * (LDSE * 2) + half * 32;
    #pragma unroll
    for (int u = 0; u < 4; u++) {
        float4 v = rv[u];
        ushort4 hh, ll;
        split1(v.x, hh.x, ll.x); split1(v.y, hh.y, ll.y);
        split1(v.z, hh.z, ll.z); split1(v.w, hh.w, ll.w);
        asm volatile("st.shared.v4.u16 [%0], {%1,%2,%3,%4};"
                     :: "r"(s_hi + off + u * 8), "h"(hh.x), "h"(hh.y), "h"(hh.z), "h"(hh.w));
        asm volatile("st.shared.v4.u16 [%0], {%1,%2,%3,%4};"
                     :: "r"(s_lo + off + u * 8), "h"(ll.x), "h"(ll.y), "h"(ll.z), "h"(ll.w));
    }
}

__device__ __forceinline__ void gemm_mma_body(
    const float* __restrict__ A, int lda, const float* __restrict__ W, int ldw,
    const float* __restrict__ bias, float* __restrict__ C, size_t ldcr, int ldcc,
    int bm, int bn, int M, int N, int kbeg, int kend, int act)
{
    __shared__ __align__(16) char smem[2 * STAGEB];
    uint32_t sb = smem_u32(smem);
    int tid = threadIdx.x;                  // 128
    int lane = tid & 31, wid = tid >> 5;
    int wm = wid >> 1, wn = wid & 1;

    float acc[2][4][4] = {};

    uint32_t a_off = ((uint32_t)(wm * 32 + (lane & 15)) * LDSE + ((lane & 16) >> 1)) * 2;
    uint32_t b_off = ((uint32_t)(wn * 32 + (lane & 7) + ((lane & 16) >> 1)) * LDSE) * 2
                     + (lane & 8) * 2;

    int nch = (kend - kbeg) / BK;
    float4 ra[4], rw[4];
    load_chunk(A, lda, bm, M, W, ldw, bn, N, kbeg, tid, ra, rw);
    store_chunk(sb, sb + PARTB, ra, tid);
    store_chunk(sb + 2 * PARTB, sb + 3 * PARTB, rw, tid);

    for (int c = 0; c < nch; c++) {
        uint32_t cb = sb + (uint32_t)(c & 1) * STAGEB;
        __syncthreads();
        bool more = (c + 1 < nch);
        if (more)
            load_chunk(A, lda, bm, M, W, ldw, bn, N, kbeg + (c + 1) * BK, tid, ra, rw);
        #pragma unroll
        for (int ks = 0; ks < 2; ks++) {
            uint32_t a_hi[2][4], a_lo[2][4], b_hi[4][2], b_lo[4][2];
            #pragma unroll
            for (int tm = 0; tm < 2; tm++) {
                uint32_t ad = cb + a_off + (uint32_t)tm * 16 * LDSE * 2 + ks * 32;
                ldsm_x4(a_hi[tm][0], a_hi[tm][1], a_hi[tm][2], a_hi[tm][3], ad);
                ldsm_x4(a_lo[tm][0], a_lo[tm][1], a_lo[tm][2], a_lo[tm][3], ad + PARTB);
            }
            #pragma unroll
            for (int tp = 0; tp < 2; tp++) {
                uint32_t bd = cb + 2 * PARTB + b_off
                            + (uint32_t)tp * 16 * LDSE * 2 + ks * 32;
                ldsm_x4(b_hi[2*tp][0], b_hi[2*tp][1], b_hi[2*tp+1][0], b_hi[2*tp+1][1], bd);
                ldsm_x4(b_lo[2*tp][0], b_lo[2*tp][1], b_lo[2*tp+1][0], b_lo[2*tp+1][1],
                        bd + PARTB);
            }
            #pragma unroll
            for (int tm = 0; tm < 2; tm++)
                #pragma unroll
                for (int tn = 0; tn < 4; tn++) {
                    mma_bf16(acc[tm][tn], a_hi[tm], b_hi[tn]);
                    mma_bf16(acc[tm][tn], a_hi[tm], b_lo[tn]);
                    mma_bf16(acc[tm][tn], a_lo[tm], b_hi[tn]);
                }
        }
        if (more) {
            uint32_t nb = sb + (uint32_t)((c + 1) & 1) * STAGEB;
            store_chunk(nb, nb + PARTB, ra, tid);
            store_chunk(nb + 2 * PARTB, nb + 3 * PARTB, rw, tid);
        }
    }

    int mrow = bm + wm * 32 + (lane >> 2);
    int ncol = bn + wn * 32 + (lane & 3) * 2;
    #pragma unroll
    for (int tm = 0; tm < 2; tm++) {
        #pragma unroll
        for (int half = 0; half < 2; half++) {
            int m = mrow + tm * 16 + half * 8;
            if (m >= M) continue;
            size_t rb = (size_t)m * ldcr;
            #pragma unroll
            for (int tn = 0; tn < 4; tn++) {
                int n = ncol + tn * 8;
                float v0 = acc[tm][tn][half * 2 + 0];
                float v1 = acc[tm][tn][half * 2 + 1];
                if (bias) { v0 += bias[n]; v1 += bias[n + 1]; }
                if (act) { v0 = fmaxf(v0, 0.f); v1 = fmaxf(v1, 0.f); }
                if (ldcc == 1 && n + 1 < N) {
                    *(float2*)(C + rb + n) = make_float2(v0, v1);
                } else {
                    if (n < N)     C[rb + (size_t)n * ldcc]       = v0;
                    if (n + 1 < N) C[rb + (size_t)(n + 1) * ldcc] = v1;
                }
            }
        }
    }
}

__global__ void __launch_bounds__(128) gemm_tc(
    const float* A, const float* W, const float* bias, float* C,
    int M, int N, int K, int act)
{
    gemm_mma_body(A, K, W, K, bias, C, N, 1,
                  blockIdx.y * 64, blockIdx.x * 64, M, N, 0, K, act);
}

__global__ void __launch_bounds__(128) gemm_tc_splitk(
    const float* A, const float* W, float* part, int M, int N, int K, int KS)
{
    int chunk = K / KS;
    int z = blockIdx.z;
    gemm_mma_body(A, K, W, K, nullptr, part + (size_t)z * M * N, N, 1,
                  blockIdx.y * 64, blockIdx.x * 64, M, N, z * chunk, (z + 1) * chunk, 0);
}

// fused q/k/vs/vo projections + knowledge projection: 1D grid, 384 CTAs
//   idx <  256: proj tiles  (z = idx/64 selects weight, 8x8 tiles of [512,512])
//   idx >= 256: kproj tiles (16x8 tiles of [1000,512])
__global__ void __launch_bounds__(128) gemm_layer_a(
    const float* __restrict__ h, const float* __restrict__ knowledge,
    const float* __restrict__ W0, const float* __restrict__ W1,
    const float* __restrict__ W2, const float* __restrict__ W3,
    const float* __restrict__ Wkn,
    float* __restrict__ qkv, float* __restrict__ kproj)
{
    int idx = blockIdx.x;
    if (idx < 256) {
        int z = idx >> 6, t = idx & 63;
        const float* W = (z == 0) ? W0 : (z == 1) ? W1 : (z == 2) ? W2 : W3;
        gemm_mma_body(h, Esz, W, Esz, nullptr, qkv + (size_t)z * Msz * Esz, Esz, 1,
                      (t >> 3) * 64, (t & 7) * 64, Msz, Esz, 0, Esz, 0);
    } else {
        int t = idx - 256;   // 0..127 -> 16 m-tiles x 8 n-tiles
        gemm_mma_body(knowledge, Esz, Wkn, Esz, nullptr, kproj, Esz, 1,
                      (t >> 3) * 64, (t & 7) * 64, 1000, Esz, 0, Esz, 0);
    }
}

// combined qk + qkp: grid (18, 2, 32)
__global__ void __launch_bounds__(128) gemm_qkqkp(
    const float* __restrict__ q, const float* __restrict__ k,
    const float* __restrict__ kproj,
    float* __restrict__ qk, float* __restrict__ qkp)
{
    int z = blockIdx.z, b = z >> 3, h = z & 7;
    const float* qa = q + (size_t)b * Ssz * Esz + h * HDsz;
    int bm = blockIdx.y * 64;
    if (blockIdx.x < 16) {
        gemm_mma_body(qa, Esz, kproj + h * HDsz, Esz, nullptr,
                      qkp + (size_t)b * Ssz * 8000 + h, 8000, 8,
                      bm, blockIdx.x * 64, Ssz, 1000, 0, HDsz, 0);
    } else {
        gemm_mma_body(qa, Esz, k + (size_t)b * Ssz * Esz + h * HDsz, Esz, nullptr,
                      qk + (size_t)z * Ssz * Ssz, Ssz, 1,
                      bm, (blockIdx.x - 16) * 64, Ssz, Ssz, 0, HDsz, 0);
    }
}

// ======== scores: gather + softmax + mask-split + pos-histogram =============
__global__ void scores_kernel(const float* __restrict__ qk, const float* __restrict__ qkp,
                              const float* __restrict__ q,
                              const int* __restrict__ know_adj,
                              const int* __restrict__ pos_mask,
                              const int* __restrict__ adj,
                              const int* __restrict__ smk, const int* __restrict__ omk,
                              const float* __restrict__ pe_k,
                              float* __restrict__ A1, float* __restrict__ A2,
                              float* __restrict__ attn_pos)
{
    int i = blockIdx.x, b = blockIdx.y;
    int tid = threadIdx.x;                  // 0..255
    __shared__ float q_sh[512];
    __shared__ float qk_sh[8 * 128];
    __shared__ float qkp_sh[128 * 9];
    __shared__ float qr[8 * 11];
    __shared__ int   ka_sh[128];
    __shared__ int   p_sh[128];

    q_sh[tid]       = q[(size_t)(b * Ssz + i) * Esz + tid];
    q_sh[tid + 256] = q[(size_t)(b * Ssz + i) * Esz + tid + 256];
    if (tid < 128) {
        int ka = know_adj[(size_t)(b * Ssz + i) * Ssz + tid];
        ka_sh[tid] = min(max(ka, 0), 999);
        int p = pos_mask[i * Ssz + tid];
        p_sh[tid] = min(max(p, 0), 10);
    }
    {
        int h = tid >> 5, j4 = (tid & 31) * 4;
        float4 v = *(const float4*)(qk + ((size_t)(b * Hn + h) * Ssz + i) * Ssz + j4);
        *(float4*)(qk_sh + h * 128 + j4) = v;
    }
    __syncthreads();

    {
        int j = tid >> 1, half = tid & 1;
        float4 g = *(const float4*)(qkp + (size_t)(b * Ssz + i) * 8000
                                    + ka_sh[j] * 8 + half * 4);
        float* dst = qkp_sh + j * 9 + half * 4;
        dst[0] = g.x; dst[1] = g.y; dst[2] = g.z; dst[3] = g.w;
    }
    if (tid < 88) {
        int h = tid / 11, p = tid % 11;
        float s = 0.f;
        const float4* pk = (const float4*)(pe_k + p * HDsz);
        const float4* qv = (const float4*)(q_sh + h * 64);
        #pragma unroll
        for (int v = 0; v < 16; v++) {
            float4 e = pk[v], qq = qv[v];
            s += qq.x * e.x + qq.y * e.y + qq.z * e.z + qq.w * e.w;
        }
        qr[h * 11 + p] = s;
    }
    __syncthreads();

    {
        int w = tid >> 5, l = tid & 31;
        float s[4];
        float m = -3.4e38f;
        #pragma unroll
        for (int t = 0; t < 4; t++) {
            int j = l + 32 * t;
            float ss = (qk_sh[w * 128 + j] + qkp_sh[j * 9 + w]
                        + qr[w * 11 + p_sh[j]]) * 0.125f;
            if (adj[(size_t)(b * Ssz + i) * Ssz + j] == 0) ss -= 1e30f;
            s[t] = ss;
            m = fmaxf(m, ss);
        }
        #pragma unroll
        for (int o = 16; o; o >>= 1) m = fmaxf(m, __shfl_xor_sync(0xffffffffu, m, o));
        float sum = 0.f;
        float e[4];
        #pragma unroll
        for (int t = 0; t < 4; t++) { e[t] = __expf(s[t] - m); sum += e[t]; }
        #pragma unroll
        for (int o = 16; o; o >>= 1) sum += __shfl_xor_sync(0xffffffffu, sum, o);
        float inv = 1.f / sum;
        size_t rbase = ((size_t)(b * Hn + w) * Ssz + i) * Ssz;
        #pragma unroll
        for (int t = 0; t < 4; t++) {
            int j = l + 32 * t;
            float attn = e[t] * inv;
            A1[rbase + j] = attn * (float)smk[(size_t)(b * Ssz + i) * Ssz + j];
            A2[rbase + j] = attn * (float)omk[(size_t)(b * Ssz + i) * Ssz + j];
            qk_sh[w * 128 + j] = attn;
        }
    }
    __syncthreads();

    if (tid < 88) {
        int h = tid / 11, p = tid % 11;
        float s = 0.f;
        for (int j = 0; j < 128; j++)
            if (p_sh[j] == p) s += qk_sh[h * 128 + j];
        attn_pos[((size_t)(b * Hn + h) * Ssz + i) * 11 + p] = s;
    }
}

// ================= attention value sum ======================================
__global__ void attnsum_kernel(const float* __restrict__ vs, const float* __restrict__ vo,
                               const float* __restrict__ A1, const float* __restrict__ A2,
                               const float* __restrict__ attn_pos,
                               const float* __restrict__ pe_v,
                               float* __restrict__ outbuf)
{
    int itile = blockIdx.x, hh = blockIdx.y, b = blockIdx.z;
    int tid = threadIdx.x;
    int grp = tid >> 6, d = tid & 63;
    __shared__ float vsh[128 * 65];

    for (int idx = tid; idx < 128 * 64; idx += 256) {
        int j = idx >> 6, dd = idx & 63;
        vsh[j * 65 + dd] = vs[(size_t)(b * Ssz + j) * Esz + hh * HDsz + dd];
    }
    __syncthreads();

    float acc[8];
    #pragma unroll
    for (int it = 0; it < 8; it++) {
        int i = itile * 32 + it * 4 + grp;
        const float* a1 = A1 + ((size_t)(b * Hn + hh) * Ssz + i) * Ssz;
        float s = 0.f;
        #pragma unroll 4
        for (int jj = 0; jj < 128; jj++) s += a1[jj] * vsh[jj * 65 + d];
        acc[it] = s;
    }
    __syncthreads();
    for (int idx = tid; idx < 128 * 64; idx += 256) {
        int j = idx >> 6, dd = idx & 63;
        vsh[j * 65 + dd] = vo[(size_t)(b * Ssz + j) * Esz + hh * HDsz + dd];
    }
    __syncthreads();
    #pragma unroll
    for (int it = 0; it < 8; it++) {
        int i = itile * 32 + it * 4 + grp;
        const float* a2 = A2 + ((size_t)(b * Hn + hh) * Ssz + i) * Ssz;
        float s = acc[it];
        #pragma unroll 4
        for (int jj = 0; jj < 128; jj++) s += a2[jj] * vsh[jj * 65 + d];
        const float* app = attn_pos + ((size_t)(b * Hn + hh) * Ssz + i) * 11;
        #pragma unroll
        for (int p = 0; p < 11; p++) s += app[p] * pe_v[p * HDsz + d];
        outbuf[(size_t)(b * Ssz + i) * Esz + hh * HDsz + d] = s;
    }
}

// ===== fused split-K reduce + bias + residual + layernorm ===================
__global__ void ln_red_kernel(const float* __restrict__ x, const float* __restrict__ part,
                              int KS, const float* __restrict__ bias,
                              const float* __restrict__ g, const float* __restrict__ bt,
                              float* __restrict__ dst)
{
    const int MN = Msz * Esz;
    int row = blockIdx.x;
    int tid = threadIdx.x;   // 256
    __shared__ float red[8];
    size_t i0 = (size_t)row * Esz + tid;
    size_t i1 = i0 + 256;
    float v0 = x[i0], v1 = x[i1];
    for (int z = 0; z < KS; z++) {
        v0 += part[(size_t)z * MN + i0];
        v1 += part[(size_t)z * MN + i1];
    }
    if (bias) { v0 += bias[tid]; v1 += bias[tid + 256]; }
    float s = v0 + v1;
    #pragma unroll
    for (int o = 16; o; o >>= 1) s += __shfl_xor_sync(0xffffffffu, s, o);
    if ((tid & 31) == 0) red[tid >> 5] = s;
    __syncthreads();
    float mean = 0.f;
    #pragma unroll
    for (int w = 0; w < 8; w++) mean += red[w];
    mean *= (1.f / 512.f);
    __syncthreads();
    float e0 = v0 - mean, e1 = v1 - mean;
    float s2 = e0 * e0 + e1 * e1;
    #pragma unroll
    for (int o = 16; o; o >>= 1) s2 += __shfl_xor_sync(0xffffffffu, s2, o);
    if ((tid & 31) == 0) red[tid >> 5] = s2;
    __syncthreads();
    float var = 0.f;
    #pragma unroll
    for (int w = 0; w < 8; w++) var += red[w];
    var *= (1.f / 512.f);
    float rstd = rsqrtf(var + 1e-5f);
    dst[i0] = e0 * rstd * g[tid] + bt[tid];
    dst[i1] = e1 * rstd * g[tid + 256] + bt[tid + 256];
}

// ===================== host orchestration ===================================
extern "C" void kernel_launch(void* const* d_in, const int* in_sizes, int n_in,
                              void* d_out, int out_size)
{
    const float* x        = (const float*)d_in[0];
    const int*   adj      = (const int*)d_in[1];
    const int*   smk      = (const int*)d_in[2];
    const int*   omk      = (const int*)d_in[3];
    const float* knowledge= (const float*)d_in[4];
    const int*   know_adj = (const int*)d_in[5];
    const int*   pos_mask = (const int*)d_in[6];
    const float* pe_k     = (const float*)d_in[7];
    const float* pe_v     = (const float*)d_in[8];
    const float* Wq       = (const float*)d_in[9];
    const float* Wk       = (const float*)d_in[10];
    const float* Wvs      = (const float*)d_in[11];
    const float* Wvo      = (const float*)d_in[12];
    const float* Wo       = (const float*)d_in[13];
    const float* Wkn      = (const float*)d_in[14];
    const float* ln1g     = (const float*)d_in[15];
    const float* ln1b     = (const float*)d_in[16];
    const float* w1       = (const float*)d_in[17];
    const float* b1       = (const float*)d_in[18];
    const float* w2       = (const float*)d_in[19];
    const float* b2       = (const float*)d_in[20];
    const float* ln2g     = (const float*)d_in[21];
    const float* ln2b     = (const float*)d_in[22];
    float* out = (float*)d_out;

    float *h, *qkv, *kproj, *A1, *A2, *ap, *asum, *ff, *part, *qkbuf, *qkp;
    cudaGetSymbolAddress((void**)&h, g_h);
    cudaGetSymbolAddress((void**)&qkv, g_qkv);
    cudaGetSymbolAddress((void**)&kproj, g_kproj);
    cudaGetSymbolAddress((void**)&A1, g_A1);
    cudaGetSymbolAddress((void**)&A2, g_A2);
    cudaGetSymbolAddress((void**)&ap, g_ap);
    cudaGetSymbolAddress((void**)&asum, g_attnsum);
    cudaGetSymbolAddress((void**)&ff, g_ff);
    cudaGetSymbolAddress((void**)&part, g_part);
    cudaGetSymbolAddress((void**)&qkbuf, g_qk);
    cudaGetSymbolAddress((void**)&qkp, g_qkp);

    const size_t EE = (size_t)Esz * Esz;
    const size_t FE = (size_t)FFsz * Esz;
    for (int l = 0; l < Lnum; l++) {
        const float* hin = (l == 0) ? x : h;
        const float* wq  = Wq  + (size_t)l * EE;
        const float* wk  = Wk  + (size_t)l * EE;
        const float* wvs = Wvs + (size_t)l * EE;
        const float* wvo = Wvo + (size_t)l * EE;
        const float* wo  = Wo  + (size_t)l * EE;
        const float* wkn = Wkn + (size_t)l * EE;

        // q,k,vs,vo projections + knowledge projection (384 CTAs)
        gemm_layer_a<<<384, 128>>>(hin, knowledge, wq, wk, wvs, wvo, wkn, qkv, kproj);
        // qk + qkp in one launch (1152 CTAs)
        gemm_qkqkp<<<dim3(18, 2, 32), 128>>>(qkv, qkv + (size_t)Msz * Esz, kproj,
                                             qkbuf, qkp);
        // scores: gather + softmax + mask-split + pos histogram
        scores_kernel<<<dim3(Ssz, Bsz), 256>>>(
            qkbuf, qkp, qkv, know_adj, pos_mask, adj, smk, omk,
            pe_k, A1, A2, ap);
        // attention value sum
        attnsum_kernel<<<dim3(4, Hn, Bsz), 256>>>(
            qkv + 2 * (size_t)Msz * Esz, qkv + 3 * (size_t)Msz * Esz,
            A1, A2, ap, pe_v, asum);
        // output projection, split-K=2 (128 CTAs) + fused reduce+LN1
        gemm_tc_splitk<<<dim3(8, 8, 2), 128>>>(asum, wo, part, Msz, Esz, Esz, 2);
        ln_red_kernel<<<Msz, 256>>>(hin, part, 2, nullptr,
                                    ln1g + l * Esz, ln1b + l * Esz, h);
        // FFN1 (256 CTAs, fused bias+relu)
        gemm_tc<<<dim3(32, 8), 128>>>(h, w1 + (size_t)l * FE, b1 + (size_t)l * FFsz,
                                      ff, Msz, FFsz, Esz, 1);
        // FFN2, split-K=4 (256 CTAs) + fused reduce+bias+LN2
        gemm_tc_splitk<<<dim3(8, 8, 4), 128>>>(ff, w2 + (size_t)l * FE, part,
                                               Msz, Esz, FFsz, 4);
        float* dst = (l == Lnum - 1) ? out : h;
        ln_red_kernel<<<Msz, 256>>>(h, part, 4, b2 + l * Esz,
                                    ln2g + l * Esz, ln2b + l * Esz, dst);
    }
}

// round 10
// speedup vs baseline: 2.5039x; 1.2679x over previous
#include <cuda_runtime.h>
#include <cuda_bf16.h>
#include <cstdint>

#define Bsz 4
#define Ssz 128
#define Esz 512
#define Hn 8
#define HDsz 64
#define FFsz 2048
#define Lnum 4
#define Msz (Bsz*Ssz)   /* 512 rows */

// ===================== scratch (static device memory) ======================
__device__ float g_h[Msz*Esz];
__device__ float g_qkv[4*Msz*Esz];
__device__ float g_kproj[1024*Esz];
__device__ float g_A1[Bsz*Hn*Ssz*Ssz];
__device__ float g_A2[Bsz*Hn*Ssz*Ssz];
__device__ float g_ap[Bsz*Hn*Ssz*11];
__device__ float g_attnsum[Msz*Esz];
__device__ float g_ff[Msz*FFsz];
__device__ float g_part[4*512*512];     // split-K partials
__device__ float g_qk[Bsz*Hn*Ssz*Ssz];
__device__ float g_qkp[512*8000];       // qkp[b,i,r,h]  (16 MB)

// ===================== helpers ==============================================
__device__ __forceinline__ void split1(float x, unsigned short& h, unsigned short& l)
{
    __nv_bfloat16 hb = __float2bfloat16(x);
    h = __bfloat16_as_ushort(hb);
    l = __bfloat16_as_ushort(__float2bfloat16(x - __bfloat162float(hb)));
}
__device__ __forceinline__ void ldsm_x4(uint32_t& r0, uint32_t& r1,
                                        uint32_t& r2, uint32_t& r3, uint32_t addr)
{
    asm volatile("ldmatrix.sync.aligned.m8n8.x4.shared.b16 {%0,%1,%2,%3}, [%4];"
                 : "=r"(r0), "=r"(r1), "=r"(r2), "=r"(r3) : "r"(addr));
}
__device__ __forceinline__ void mma_bf16(float* c, const uint32_t* a, const uint32_t* b)
{
    asm volatile("mma.sync.aligned.m16n8k16.row.col.f32.bf16.bf16.f32 "
                 "{%0,%1,%2,%3},{%4,%5,%6,%7},{%8,%9},{%0,%1,%2,%3};"
                 : "+f"(c[0]), "+f"(c[1]), "+f"(c[2]), "+f"(c[3])
                 : "r"(a[0]), "r"(a[1]), "r"(a[2]), "r"(a[3]), "r"(b[0]), "r"(b[1]));
}
__device__ __forceinline__ uint32_t smem_u32(const void* p) {
    uint32_t a;
    asm("{ .reg .u64 t; cvta.to.shared.u64 t, %1; cvt.u32.u64 %0, t; }" : "=r"(a) : "l"(p));
    return a;
}

// ===================== tensor-core bf16x3 GEMM ==============================
// C[m,n] = sum_k A[m,k] * W[n,k] over [kbeg,kend).
// Reg prefetch + smem double buffer -> ONE sync per K-chunk.
// 64x64 CTA tile, 128 threads (2m x 2n warps, warp tile 32x32), BK=32.
#define BK 32
#define LDSE 40                 /* bf16 elems per smem row (80 B) */
#define PARTB (64*LDSE*2)       /* 5120 B per matrix part */
#define STAGEB (4*PARTB)        /* 20480 B per stage */

__device__ __forceinline__ void load_chunk(
    const float* __restrict__ A, int lda, int row0a, int Ma,
    const float* __restrict__ W, int ldw, int row0w, int Nw,
    int k0, int tid, float4* ra, float4* rw)
{
    int r = tid >> 1, half = tid & 1;
    int ga = min(row0a + r, Ma - 1);
    int gw = min(row0w + r, Nw - 1);
    const float4* pa = (const float4*)(A + (size_t)ga * lda + k0 + half * 16);
    const float4* pw = (const float4*)(W + (size_t)gw * ldw + k0 + half * 16);
    #pragma unroll
    for (int u = 0; u < 4; u++) { ra[u] = pa[u]; rw[u] = pw[u]; }
}

__device__ __forceinline__ void store_chunk(uint32_t s_hi, uint32_t s_lo,
                                            const float4* rv, int tid)
{
    int r = tid >> 1, half = tid & 1;
    uint32_t off = (uint32_t)r * (LDSE * 2) + half * 32;
    #pragma unroll
    for (int u = 0; u < 4; u++) {
        float4 v = rv[u];
        ushort4 hh, ll;
        split1(v.x, hh.x, ll.x); split1(v.y, hh.y, ll.y);
        split1(v.z, hh.z, ll.z); split1(v.w, hh.w, ll.w);
        asm volatile("st.shared.v4.u16 [%0], {%1,%2,%3,%4};"
                     :: "r"(s_hi + off + u * 8), "h"(hh.x), "h"(hh.y), "h"(hh.z), "h"(hh.w));
        asm volatile("st.shared.v4.u16 [%0], {%1,%2,%3,%4};"
                     :: "r"(s_lo + off + u * 8), "h"(ll.x), "h"(ll.y), "h"(ll.z), "h"(ll.w));
    }
}

__device__ __forceinline__ void gemm_mma_body(
    const float* __restrict__ A, int lda, const float* __restrict__ W, int ldw,
    const float* __restrict__ bias, float* __restrict__ C, size_t ldcr, int ldcc,
    int bm, int bn, int M, int N, int kbeg, int kend, int act)
{
    __shared__ __align__(16) char smem[2 * STAGEB];
    uint32_t sb = smem_u32(smem);
    int tid = threadIdx.x;                  // 128
    int lane = tid & 31, wid = tid >> 5;
    int wm = wid >> 1, wn = wid & 1;

    float acc[2][4][4] = {};

    uint32_t a_off = ((uint32_t)(wm * 32 + (lane & 15)) * LDSE + ((lane & 16) >> 1)) * 2;
    uint32_t b_off = ((uint32_t)(wn * 32 + (lane & 7) + ((lane & 16) >> 1)) * LDSE) * 2
                     + (lane & 8) * 2;

    int nch = (kend - kbeg) / BK;
    float4 ra[4], rw[4];
    load_chunk(A, lda, bm, M, W, ldw, bn, N, kbeg, tid, ra, rw);
    store_chunk(sb, sb + PARTB, ra, tid);
    store_chunk(sb + 2 * PARTB, sb + 3 * PARTB, rw, tid);

    for (int c = 0; c < nch; c++) {
        uint32_t cb = sb + (uint32_t)(c & 1) * STAGEB;
        __syncthreads();
        bool more = (c + 1 < nch);
        if (more)
            load_chunk(A, lda, bm, M, W, ldw, bn, N, kbeg + (c + 1) * BK, tid, ra, rw);
        #pragma unroll
        for (int ks = 0; ks < 2; ks++) {
            uint32_t a_hi[2][4], a_lo[2][4], b_hi[4][2], b_lo[4][2];
            #pragma unroll
            for (int tm = 0; tm < 2; tm++) {
                uint32_t ad = cb + a_off + (uint32_t)tm * 16 * LDSE * 2 + ks * 32;
                ldsm_x4(a_hi[tm][0], a_hi[tm][1], a_hi[tm][2], a_hi[tm][3], ad);
                ldsm_x4(a_lo[tm][0], a_lo[tm][1], a_lo[tm][2], a_lo[tm][3], ad + PARTB);
            }
            #pragma unroll
            for (int tp = 0; tp < 2; tp++) {
                uint32_t bd = cb + 2 * PARTB + b_off
                            + (uint32_t)tp * 16 * LDSE * 2 + ks * 32;
                ldsm_x4(b_hi[2*tp][0], b_hi[2*tp][1], b_hi[2*tp+1][0], b_hi[2*tp+1][1], bd);
                ldsm_x4(b_lo[2*tp][0], b_lo[2*tp][1], b_lo[2*tp+1][0], b_lo[2*tp+1][1],
                        bd + PARTB);
            }
            #pragma unroll
            for (int tm = 0; tm < 2; tm++)
                #pragma unroll
                for (int tn = 0; tn < 4; tn++) {
                    mma_bf16(acc[tm][tn], a_hi[tm], b_hi[tn]);
                    mma_bf16(acc[tm][tn], a_hi[tm], b_lo[tn]);
                    mma_bf16(acc[tm][tn], a_lo[tm], b_hi[tn]);
                }
        }
        if (more) {
            uint32_t nb = sb + (uint32_t)((c + 1) & 1) * STAGEB;
            store_chunk(nb, nb + PARTB, ra, tid);
            store_chunk(nb + 2 * PARTB, nb + 3 * PARTB, rw, tid);
        }
    }

    int mrow = bm + wm * 32 + (lane >> 2);
    int ncol = bn + wn * 32 + (lane & 3) * 2;
    #pragma unroll
    for (int tm = 0; tm < 2; tm++) {
        #pragma unroll
        for (int half = 0; half < 2; half++) {
            int m = mrow + tm * 16 + half * 8;
            if (m >= M) continue;
            size_t rb = (size_t)m * ldcr;
            #pragma unroll
            for (int tn = 0; tn < 4; tn++) {
                int n = ncol + tn * 8;
                float v0 = acc[tm][tn][half * 2 + 0];
                float v1 = acc[tm][tn][half * 2 + 1];
                if (bias) { v0 += bias[n]; v1 += bias[n + 1]; }
                if (act) { v0 = fmaxf(v0, 0.f); v1 = fmaxf(v1, 0.f); }
                if (ldcc == 1 && n + 1 < N) {
                    *(float2*)(C + rb + n) = make_float2(v0, v1);
                } else {
                    if (n < N)     C[rb + (size_t)n * ldcc]       = v0;
                    if (n + 1 < N) C[rb + (size_t)(n + 1) * ldcc] = v1;
                }
            }
        }
    }
}

__global__ void __launch_bounds__(128) gemm_tc(
    const float* A, const float* W, const float* bias, float* C,
    int M, int N, int K, int act)
{
    gemm_mma_body(A, K, W, K, bias, C, N, 1,
                  blockIdx.y * 64, blockIdx.x * 64, M, N, 0, K, act);
}

__global__ void __launch_bounds__(128) gemm_tc_splitk(
    const float* A, const float* W, float* part, int M, int N, int K, int KS)
{
    int chunk = K / KS;
    int z = blockIdx.z;
    gemm_mma_body(A, K, W, K, nullptr, part + (size_t)z * M * N, N, 1,
                  blockIdx.y * 64, blockIdx.x * 64, M, N, z * chunk, (z + 1) * chunk, 0);
}

// fused q/k/vs/vo projections + knowledge projection: 1D grid, 384 CTAs
__global__ void __launch_bounds__(128) gemm_layer_a(
    const float* __restrict__ h, const float* __restrict__ knowledge,
    const float* __restrict__ W0, const float* __restrict__ W1,
    const float* __restrict__ W2, const float* __restrict__ W3,
    const float* __restrict__ Wkn,
    float* __restrict__ qkv, float* __restrict__ kproj)
{
    int idx = blockIdx.x;
    if (idx < 256) {
        int z = idx >> 6, t = idx & 63;
        const float* W = (z == 0) ? W0 : (z == 1) ? W1 : (z == 2) ? W2 : W3;
        gemm_mma_body(h, Esz, W, Esz, nullptr, qkv + (size_t)z * Msz * Esz, Esz, 1,
                      (t >> 3) * 64, (t & 7) * 64, Msz, Esz, 0, Esz, 0);
    } else {
        int t = idx - 256;   // 0..127 -> 16 m-tiles x 8 n-tiles
        gemm_mma_body(knowledge, Esz, Wkn, Esz, nullptr, kproj, Esz, 1,
                      (t >> 3) * 64, (t & 7) * 64, 1000, Esz, 0, Esz, 0);
    }
}

// combined qk + qkp: grid (18, 2, 32)
__global__ void __launch_bounds__(128) gemm_qkqkp(
    const float* __restrict__ q, const float* __restrict__ k,
    const float* __restrict__ kproj,
    float* __restrict__ qk, float* __restrict__ qkp)
{
    int z = blockIdx.z, b = z >> 3, h = z & 7;
    const float* qa = q + (size_t)b * Ssz * Esz + h * HDsz;
    int bm = blockIdx.y * 64;
    if (blockIdx.x < 16) {
        gemm_mma_body(qa, Esz, kproj + h * HDsz, Esz, nullptr,
                      qkp + (size_t)b * Ssz * 8000 + h, 8000, 8,
                      bm, blockIdx.x * 64, Ssz, 1000, 0, HDsz, 0);
    } else {
        gemm_mma_body(qa, Esz, k + (size_t)b * Ssz * Esz + h * HDsz, Esz, nullptr,
                      qk + (size_t)z * Ssz * Ssz, Ssz, 1,
                      bm, (blockIdx.x - 16) * 64, Ssz, Ssz, 0, HDsz, 0);
    }
}

// ======== scores: gather + softmax + mask-split + pos-histogram =============
__global__ void scores_kernel(const float* __restrict__ qk, const float* __restrict__ qkp,
                              const float* __restrict__ q,
                              const int* __restrict__ know_adj,
                              const int* __restrict__ pos_mask,
                              const int* __restrict__ adj,
                              const int* __restrict__ smk, const int* __restrict__ omk,
                              const float* __restrict__ pe_k,
                              float* __restrict__ A1, float* __restrict__ A2,
                              float* __restrict__ attn_pos)
{
    int i = blockIdx.x, b = blockIdx.y;
    int tid = threadIdx.x;                  // 0..255
    __shared__ float q_sh[512];
    __shared__ float qk_sh[8 * 128];
    __shared__ float qkp_sh[128 * 9];
    __shared__ float qr[8 * 11];
    __shared__ int   ka_sh[128];
    __shared__ int   p_sh[128];

    q_sh[tid]       = q[(size_t)(b * Ssz + i) * Esz + tid];
    q_sh[tid + 256] = q[(size_t)(b * Ssz + i) * Esz + tid + 256];
    if (tid < 128) {
        int ka = know_adj[(size_t)(b * Ssz + i) * Ssz + tid];
        ka_sh[tid] = min(max(ka, 0), 999);
        int p = pos_mask[i * Ssz + tid];
        p_sh[tid] = min(max(p, 0), 10);
    }
    {
        int h = tid >> 5, j4 = (tid & 31) * 4;
        float4 v = *(const float4*)(qk + ((size_t)(b * Hn + h) * Ssz + i) * Ssz + j4);
        *(float4*)(qk_sh + h * 128 + j4) = v;
    }
    __syncthreads();

    {
        int j = tid >> 1, half = tid & 1;
        float4 g = *(const float4*)(qkp + (size_t)(b * Ssz + i) * 8000
                                    + ka_sh[j] * 8 + half * 4);
        float* dst = qkp_sh + j * 9 + half * 4;
        dst[0] = g.x; dst[1] = g.y; dst[2] = g.z; dst[3] = g.w;
    }
    if (tid < 88) {
        int h = tid / 11, p = tid % 11;
        float s = 0.f;
        const float4* pk = (const float4*)(pe_k + p * HDsz);
        const float4* qv = (const float4*)(q_sh + h * 64);
        #pragma unroll
        for (int v = 0; v < 16; v++) {
            float4 e = pk[v], qq = qv[v];
            s += qq.x * e.x + qq.y * e.y + qq.z * e.z + qq.w * e.w;
        }
        qr[h * 11 + p] = s;
    }
    __syncthreads();

    {
        int w = tid >> 5, l = tid & 31;
        float s[4];
        float m = -3.4e38f;
        #pragma unroll
        for (int t = 0; t < 4; t++) {
            int j = l + 32 * t;
            float ss = (qk_sh[w * 128 + j] + qkp_sh[j * 9 + w]
                        + qr[w * 11 + p_sh[j]]) * 0.125f;
            if (adj[(size_t)(b * Ssz + i) * Ssz + j] == 0) ss -= 1e30f;
            s[t] = ss;
            m = fmaxf(m, ss);
        }
        #pragma unroll
        for (int o = 16; o; o >>= 1) m = fmaxf(m, __shfl_xor_sync(0xffffffffu, m, o));
        float sum = 0.f;
        float e[4];
        #pragma unroll
        for (int t = 0; t < 4; t++) { e[t] = __expf(s[t] - m); sum += e[t]; }
        #pragma unroll
        for (int o = 16; o; o >>= 1) sum += __shfl_xor_sync(0xffffffffu, sum, o);
        float inv = 1.f / sum;
        size_t rbase = ((size_t)(b * Hn + w) * Ssz + i) * Ssz;
        #pragma unroll
        for (int t = 0; t < 4; t++) {
            int j = l + 32 * t;
            float attn = e[t] * inv;
            A1[rbase + j] = attn * (float)smk[(size_t)(b * Ssz + i) * Ssz + j];
            A2[rbase + j] = attn * (float)omk[(size_t)(b * Ssz + i) * Ssz + j];
            qk_sh[w * 128 + j] = attn;
        }
    }
    __syncthreads();

    if (tid < 88) {
        int h = tid / 11, p = tid % 11;
        float s = 0.f;
        for (int j = 0; j < 128; j++)
            if (p_sh[j] == p) s += qk_sh[h * 128 + j];
        attn_pos[((size_t)(b * Hn + h) * Ssz + i) * 11 + p] = s;
    }
}

// ================= attention value sum (transposed V, float4 j-loop) ========
// grid (8 itile, 8 h, 4 b), 128 threads (2 i-groups x 64 d), 8 i per thread-grp
#define VPAD 132
__global__ void __launch_bounds__(128) attnsum_kernel(
    const float* __restrict__ vs, const float* __restrict__ vo,
    const float* __restrict__ A1, const float* __restrict__ A2,
    const float* __restrict__ attn_pos, const float* __restrict__ pe_v,
    float* __restrict__ outbuf)
{
    int itile = blockIdx.x, hh = blockIdx.y, b = blockIdx.z;
    int tid = threadIdx.x;
    int grp = tid >> 6, d = tid & 63;
    int i0 = itile * 16 + grp * 8;
    __shared__ float vsh[64 * VPAD];   // vsh[d][j] transposed

    // stage vs transposed
    for (int idx = tid; idx < 128 * 64; idx += 128) {
        int j = idx >> 6, dd = idx & 63;
        vsh[dd * VPAD + j] = vs[(size_t)(b * Ssz + j) * Esz + hh * HDsz + dd];
    }
    __syncthreads();

    float4 acc4[8];
    #pragma unroll
    for (int it = 0; it < 8; it++) acc4[it] = make_float4(0.f, 0.f, 0.f, 0.f);

    const float4* a1r[8];
    #pragma unroll
    for (int it = 0; it < 8; it++)
        a1r[it] = (const float4*)(A1 + ((size_t)(b * Hn + hh) * Ssz + i0 + it) * Ssz);

    const float4* vrow = (const float4*)(vsh + d * VPAD);
    #pragma unroll 4
    for (int j4 = 0; j4 < 32; j4++) {
        float4 v = vrow[j4];
        #pragma unroll
        for (int it = 0; it < 8; it++) {
            float4 a = a1r[it][j4];
            acc4[it].x += a.x * v.x; acc4[it].y += a.y * v.y;
            acc4[it].z += a.z * v.z; acc4[it].w += a.w * v.w;
        }
    }
    __syncthreads();

    // stage vo transposed
    for (int idx = tid; idx < 128 * 64; idx += 128) {
        int j = idx >> 6, dd = idx & 63;
        vsh[dd * VPAD + j] = vo[(size_t)(b * Ssz + j) * Esz + hh * HDsz + dd];
    }
    __syncthreads();

    #pragma unroll
    for (int it = 0; it < 8; it++)
        a1r[it] = (const float4*)(A2 + ((size_t)(b * Hn + hh) * Ssz + i0 + it) * Ssz);

    #pragma unroll 4
    for (int j4 = 0; j4 < 32; j4++) {
        float4 v = vrow[j4];
        #pragma unroll
        for (int it = 0; it < 8; it++) {
            float4 a = a1r[it][j4];
            acc4[it].x += a.x * v.x; acc4[it].y += a.y * v.y;
            acc4[it].z += a.z * v.z; acc4[it].w += a.w * v.w;
        }
    }

    #pragma unroll
    for (int it = 0; it < 8; it++) {
        int i = i0 + it;
        float s = (acc4[it].x + acc4[it].y) + (acc4[it].z + acc4[it].w);
        const float* app = attn_pos + ((size_t)(b * Hn + hh) * Ssz + i) * 11;
        #pragma unroll
        for (int p = 0; p < 11; p++) s += app[p] * pe_v[p * HDsz + d];
        outbuf[(size_t)(b * Ssz + i) * Esz + hh * HDsz + d] = s;
    }
}

// ===== fused split-K reduce + bias + residual + layernorm ===================
__global__ void ln_red_kernel(const float* __restrict__ x, const float* __restrict__ part,
                              int KS, const float* __restrict__ bias,
                              const float* __restrict__ g, const float* __restrict__ bt,
                              float* __restrict__ dst)
{
    const int MN = Msz * Esz;
    int row = blockIdx.x;
    int tid = threadIdx.x;   // 256
    __shared__ float red[8];
    size_t i0 = (size_t)row * Esz + tid;
    size_t i1 = i0 + 256;
    float v0 = x[i0], v1 = x[i1];
    for (int z = 0; z < KS; z++) {
        v0 += part[(size_t)z * MN + i0];
        v1 += part[(size_t)z * MN + i1];
    }
    if (bias) { v0 += bias[tid]; v1 += bias[tid + 256]; }
    float s = v0 + v1;
    #pragma unroll
    for (int o = 16; o; o >>= 1) s += __shfl_xor_sync(0xffffffffu, s, o);
    if ((tid & 31) == 0) red[tid >> 5] = s;
    __syncthreads();
    float mean = 0.f;
    #pragma unroll
    for (int w = 0; w < 8; w++) mean += red[w];
    mean *= (1.f / 512.f);
    __syncthreads();
    float e0 = v0 - mean, e1 = v1 - mean;
    float s2 = e0 * e0 + e1 * e1;
    #pragma unroll
    for (int o = 16; o; o >>= 1) s2 += __shfl_xor_sync(0xffffffffu, s2, o);
    if ((tid & 31) == 0) red[tid >> 5] = s2;
    __syncthreads();
    float var = 0.f;
    #pragma unroll
    for (int w = 0; w < 8; w++) var += red[w];
    var *= (1.f / 512.f);
    float rstd = rsqrtf(var + 1e-5f);
    dst[i0] = e0 * rstd * g[tid] + bt[tid];
    dst[i1] = e1 * rstd * g[tid + 256] + bt[tid + 256];
}

// ===================== host orchestration ===================================
extern "C" void kernel_launch(void* const* d_in, const int* in_sizes, int n_in,
                              void* d_out, int out_size)
{
    const float* x        = (const float*)d_in[0];
    const int*   adj      = (const int*)d_in[1];
    const int*   smk      = (const int*)d_in[2];
    const int*   omk      = (const int*)d_in[3];
    const float* knowledge= (const float*)d_in[4];
    const int*   know_adj = (const int*)d_in[5];
    const int*   pos_mask = (const int*)d_in[6];
    const float* pe_k     = (const float*)d_in[7];
    const float* pe_v     = (const float*)d_in[8];
    const float* Wq       = (const float*)d_in[9];
    const float* Wk       = (const float*)d_in[10];
    const float* Wvs      = (const float*)d_in[11];
    const float* Wvo      = (const float*)d_in[12];
    const float* Wo       = (const float*)d_in[13];
    const float* Wkn      = (const float*)d_in[14];
    const float* ln1g     = (const float*)d_in[15];
    const float* ln1b     = (const float*)d_in[16];
    const float* w1       = (const float*)d_in[17];
    const float* b1       = (const float*)d_in[18];
    const float* w2       = (const float*)d_in[19];
    const float* b2       = (const float*)d_in[20];
    const float* ln2g     = (const float*)d_in[21];
    const float* ln2b     = (const float*)d_in[22];
    float* out = (float*)d_out;

    float *h, *qkv, *kproj, *A1, *A2, *ap, *asum, *ff, *part, *qkbuf, *qkp;
    cudaGetSymbolAddress((void**)&h, g_h);
    cudaGetSymbolAddress((void**)&qkv, g_qkv);
    cudaGetSymbolAddress((void**)&kproj, g_kproj);
    cudaGetSymbolAddress((void**)&A1, g_A1);
    cudaGetSymbolAddress((void**)&A2, g_A2);
    cudaGetSymbolAddress((void**)&ap, g_ap);
    cudaGetSymbolAddress((void**)&asum, g_attnsum);
    cudaGetSymbolAddress((void**)&ff, g_ff);
    cudaGetSymbolAddress((void**)&part, g_part);
    cudaGetSymbolAddress((void**)&qkbuf, g_qk);
    cudaGetSymbolAddress((void**)&qkp, g_qkp);

    const size_t EE = (size_t)Esz * Esz;
    const size_t FE = (size_t)FFsz * Esz;
    for (int l = 0; l < Lnum; l++) {
        const float* hin = (l == 0) ? x : h;
        const float* wq  = Wq  + (size_t)l * EE;
        const float* wk  = Wk  + (size_t)l * EE;
        const float* wvs = Wvs + (size_t)l * EE;
        const float* wvo = Wvo + (size_t)l * EE;
        const float* wo  = Wo  + (size_t)l * EE;
        const float* wkn = Wkn + (size_t)l * EE;

        // q,k,vs,vo projections + knowledge projection (384 CTAs)
        gemm_layer_a<<<384, 128>>>(hin, knowledge, wq, wk, wvs, wvo, wkn, qkv, kproj);
        // qk + qkp in one launch (1152 CTAs)
        gemm_qkqkp<<<dim3(18, 2, 32), 128>>>(qkv, qkv + (size_t)Msz * Esz, kproj,
                                             qkbuf, qkp);
        // scores: gather + softmax + mask-split + pos histogram
        scores_kernel<<<dim3(Ssz, Bsz), 256>>>(
            qkbuf, qkp, qkv, know_adj, pos_mask, adj, smk, omk,
            pe_k, A1, A2, ap);
        // attention value sum (256 CTAs)
        attnsum_kernel<<<dim3(8, Hn, Bsz), 128>>>(
            qkv + 2 * (size_t)Msz * Esz, qkv + 3 * (size_t)Msz * Esz,
            A1, A2, ap, pe_v, asum);
        // output projection, split-K=2 (128 CTAs) + fused reduce+LN1
        gemm_tc_splitk<<<dim3(8, 8, 2), 128>>>(asum, wo, part, Msz, Esz, Esz, 2);
        ln_red_kernel<<<Msz, 256>>>(hin, part, 2, nullptr,
                                    ln1g + l * Esz, ln1b + l * Esz, h);
        // FFN1 (256 CTAs, fused bias+relu)
        gemm_tc<<<dim3(32, 8), 128>>>(h, w1 + (size_t)l * FE, b1 + (size_t)l * FFsz,
                                      ff, Msz, FFsz, Esz, 1);
        // FFN2, split-K=4 (256 CTAs) + fused reduce+bias+LN2
        gemm_tc_splitk<<<dim3(8, 8, 4), 128>>>(ff, w2 + (size_t)l * FE, part,
                                               Msz, Esz, FFsz, 4);
        float* dst = (l == Lnum - 1) ? out : h;
        ln_red_kernel<<<Msz, 256>>>(h, part, 4, b2 + l * Esz,
                                    ln2g + l * Esz, ln2b + l * Esz, dst);
    }
}

// round 11
// speedup vs baseline: 2.6011x; 1.0388x over previous
#include <cuda_runtime.h>
#include <cuda_bf16.h>
#include <cstdint>

#define Bsz 4
#define Ssz 128
#define Esz 512
#define Hn 8
#define HDsz 64
#define FFsz 2048
#define Lnum 4
#define Msz (Bsz*Ssz)   /* 512 rows */
#define KEXT 288        /* packed attn K: 128 + 128 + 11 -> pad 288 */

// ===================== scratch (static device memory) ======================
__device__ float g_h[Msz*Esz];
__device__ float g_qkv[4*Msz*Esz];
__device__ float g_kproj[1024*Esz];
__device__ float g_attnsum[Msz*Esz];
__device__ float g_ff[Msz*FFsz];
__device__ float g_part[4*512*512];     // split-K partials
__device__ float g_qk[Bsz*Hn*Ssz*Ssz];
__device__ float g_qkp[512*8000];       // qkp[b,i,r,h]  (16 MB)
__device__ float g_Aext[Bsz*Hn*Ssz*KEXT];   // [b,h,i, 288]
__device__ float g_Wext[Bsz*Hn*HDsz*KEXT];  // [b,h,d, 288]

// ===================== helpers ==============================================
__device__ __forceinline__ void split1(float x, unsigned short& h, unsigned short& l)
{
    __nv_bfloat16 hb = __float2bfloat16(x);
    h = __bfloat16_as_ushort(hb);
    l = __bfloat16_as_ushort(__float2bfloat16(x - __bfloat162float(hb)));
}
__device__ __forceinline__ void ldsm_x4(uint32_t& r0, uint32_t& r1,
                                        uint32_t& r2, uint32_t& r3, uint32_t addr)
{
    asm volatile("ldmatrix.sync.aligned.m8n8.x4.shared.b16 {%0,%1,%2,%3}, [%4];"
                 : "=r"(r0), "=r"(r1), "=r"(r2), "=r"(r3) : "r"(addr));
}
__device__ __forceinline__ void mma_bf16(float* c, const uint32_t* a, const uint32_t* b)
{
    asm volatile("mma.sync.aligned.m16n8k16.row.col.f32.bf16.bf16.f32 "
                 "{%0,%1,%2,%3},{%4,%5,%6,%7},{%8,%9},{%0,%1,%2,%3};"
                 : "+f"(c[0]), "+f"(c[1]), "+f"(c[2]), "+f"(c[3])
                 : "r"(a[0]), "r"(a[1]), "r"(a[2]), "r"(a[3]), "r"(b[0]), "r"(b[1]));
}
__device__ __forceinline__ uint32_t smem_u32(const void* p) {
    uint32_t a;
    asm("{ .reg .u64 t; cvta.to.shared.u64 t, %1; cvt.u32.u64 %0, t; }" : "=r"(a) : "l"(p));
    return a;
}

// ===================== tensor-core bf16x3 GEMM ==============================
#define BK 32
#define LDSE 40
#define PARTB (64*LDSE*2)
#define STAGEB (4*PARTB)

__device__ __forceinline__ void load_chunk(
    const float* __restrict__ A, int lda, int row0a, int Ma,
    const float* __restrict__ W, int ldw, int row0w, int Nw,
    int k0, int tid, float4* ra, float4* rw)
{
    int r = tid >> 1, half = tid & 1;
    int ga = min(row0a + r, Ma - 1);
    int gw = min(row0w + r, Nw - 1);
    const float4* pa = (const float4*)(A + (size_t)ga * lda + k0 + half * 16);
    const float4* pw = (const float4*)(W + (size_t)gw * ldw + k0 + half * 16);
    #pragma unroll
    for (int u = 0; u < 4; u++) { ra[u] = pa[u]; rw[u] = pw[u]; }
}

__device__ __forceinline__ void store_chunk(uint32_t s_hi, uint32_t s_lo,
                                            const float4* rv, int tid)
{
    int r = tid >> 1, half = tid & 1;
    uint32_t off = (uint32_t)r * (LDSE * 2) + half * 32;
    #pragma unroll
    for (int u = 0; u < 4; u++) {
        float4 v = rv[u];
        ushort4 hh, ll;
        split1(v.x, hh.x, ll.x); split1(v.y, hh.y, ll.y);
        split1(v.z, hh.z, ll.z); split1(v.w, hh.w, ll.w);
        asm volatile("st.shared.v4.u16 [%0], {%1,%2,%3,%4};"
                     :: "r"(s_hi + off + u * 8), "h"(hh.x), "h"(hh.y), "h"(hh.z), "h"(hh.w));
        asm volatile("st.shared.v4.u16 [%0], {%1,%2,%3,%4};"
                     :: "r"(s_lo + off + u * 8), "h"(ll.x), "h"(ll.y), "h"(ll.z), "h"(ll.w));
    }
}

__device__ __forceinline__ void gemm_mma_body(
    const float* __restrict__ A, int lda, const float* __restrict__ W, int ldw,
    const float* __restrict__ bias, float* __restrict__ C, size_t ldcr, int ldcc,
    int bm, int bn, int M, int N, int kbeg, int kend, int act)
{
    __shared__ __align__(16) char smem[2 * STAGEB];
    uint32_t sb = smem_u32(smem);
    int tid = threadIdx.x;                  // 128
    int lane = tid & 31, wid = tid >> 5;
    int wm = wid >> 1, wn = wid & 1;

    float acc[2][4][4] = {};

    uint32_t a_off = ((uint32_t)(wm * 32 + (lane & 15)) * LDSE + ((lane & 16) >> 1)) * 2;
    uint32_t b_off = ((uint32_t)(wn * 32 + (lane & 7) + ((lane & 16) >> 1)) * LDSE) * 2
                     + (lane & 8) * 2;

    int nch = (kend - kbeg) / BK;
    float4 ra[4], rw[4];
    load_chunk(A, lda, bm, M, W, ldw, bn, N, kbeg, tid, ra, rw);
    store_chunk(sb, sb + PARTB, ra, tid);
    store_chunk(sb + 2 * PARTB, sb + 3 * PARTB, rw, tid);

    for (int c = 0; c < nch; c++) {
        uint32_t cb = sb + (uint32_t)(c & 1) * STAGEB;
        __syncthreads();
        bool more = (c + 1 < nch);
        if (more)
            load_chunk(A, lda, bm, M, W, ldw, bn, N, kbeg + (c + 1) * BK, tid, ra, rw);
        #pragma unroll
        for (int ks = 0; ks < 2; ks++) {
            uint32_t a_hi[2][4], a_lo[2][4], b_hi[4][2], b_lo[4][2];
            #pragma unroll
            for (int tm = 0; tm < 2; tm++) {
                uint32_t ad = cb + a_off + (uint32_t)tm * 16 * LDSE * 2 + ks * 32;
                ldsm_x4(a_hi[tm][0], a_hi[tm][1], a_hi[tm][2], a_hi[tm][3], ad);
                ldsm_x4(a_lo[tm][0], a_lo[tm][1], a_lo[tm][2], a_lo[tm][3], ad + PARTB);
            }
            #pragma unroll
            for (int tp = 0; tp < 2; tp++) {
                uint32_t bd = cb + 2 * PARTB + b_off
                            + (uint32_t)tp * 16 * LDSE * 2 + ks * 32;
                ldsm_x4(b_hi[2*tp][0], b_hi[2*tp][1], b_hi[2*tp+1][0], b_hi[2*tp+1][1], bd);
                ldsm_x4(b_lo[2*tp][0], b_lo[2*tp][1], b_lo[2*tp+1][0], b_lo[2*tp+1][1],
                        bd + PARTB);
            }
            #pragma unroll
            for (int tm = 0; tm < 2; tm++)
                #pragma unroll
                for (int tn = 0; tn < 4; tn++) {
                    mma_bf16(acc[tm][tn], a_hi[tm], b_hi[tn]);
                    mma_bf16(acc[tm][tn], a_hi[tm], b_lo[tn]);
                    mma_bf16(acc[tm][tn], a_lo[tm], b_hi[tn]);
                }
        }
        if (more) {
            uint32_t nb = sb + (uint32_t)((c + 1) & 1) * STAGEB;
            store_chunk(nb, nb + PARTB, ra, tid);
            store_chunk(nb + 2 * PARTB, nb + 3 * PARTB, rw, tid);
        }
    }

    int mrow = bm + wm * 32 + (lane >> 2);
    int ncol = bn + wn * 32 + (lane & 3) * 2;
    #pragma unroll
    for (int tm = 0; tm < 2; tm++) {
        #pragma unroll
        for (int half = 0; half < 2; half++) {
            int m = mrow + tm * 16 + half * 8;
            if (m >= M) continue;
            size_t rb = (size_t)m * ldcr;
            #pragma unroll
            for (int tn = 0; tn < 4; tn++) {
                int n = ncol + tn * 8;
                float v0 = acc[tm][tn][half * 2 + 0];
                float v1 = acc[tm][tn][half * 2 + 1];
                if (bias) { v0 += bias[n]; v1 += bias[n + 1]; }
                if (act) { v0 = fmaxf(v0, 0.f); v1 = fmaxf(v1, 0.f); }
                if (ldcc == 1 && n + 1 < N) {
                    *(float2*)(C + rb + n) = make_float2(v0, v1);
                } else {
                    if (n < N)     C[rb + (size_t)n * ldcc]       = v0;
                    if (n + 1 < N) C[rb + (size_t)(n + 1) * ldcc] = v1;
                }
            }
        }
    }
}

__global__ void __launch_bounds__(128) gemm_tc(
    const float* A, const float* W, const float* bias, float* C,
    int M, int N, int K, int act)
{
    gemm_mma_body(A, K, W, K, bias, C, N, 1,
                  blockIdx.y * 64, blockIdx.x * 64, M, N, 0, K, act);
}

__global__ void __launch_bounds__(128) gemm_tc_splitk(
    const float* A, const float* W, float* part, int M, int N, int K, int KS)
{
    int chunk = K / KS;
    int z = blockIdx.z;
    gemm_mma_body(A, K, W, K, nullptr, part + (size_t)z * M * N, N, 1,
                  blockIdx.y * 64, blockIdx.x * 64, M, N, z * chunk, (z + 1) * chunk, 0);
}

// fused q/k/vs/vo projections + knowledge projection: 1D grid, 384 CTAs
__global__ void __launch_bounds__(128) gemm_layer_a(
    const float* __restrict__ h, const float* __restrict__ knowledge,
    const float* __restrict__ W0, const float* __restrict__ W1,
    const float* __restrict__ W2, const float* __restrict__ W3,
    const float* __restrict__ Wkn,
    float* __restrict__ qkv, float* __restrict__ kproj)
{
    int idx = blockIdx.x;
    if (idx < 256) {
        int z = idx >> 6, t = idx & 63;
        const float* W = (z == 0) ? W0 : (z == 1) ? W1 : (z == 2) ? W2 : W3;
        gemm_mma_body(h, Esz, W, Esz, nullptr, qkv + (size_t)z * Msz * Esz, Esz, 1,
                      (t >> 3) * 64, (t & 7) * 64, Msz, Esz, 0, Esz, 0);
    } else {
        int t = idx - 256;
        gemm_mma_body(knowledge, Esz, Wkn, Esz, nullptr, kproj, Esz, 1,
                      (t >> 3) * 64, (t & 7) * 64, 1000, Esz, 0, Esz, 0);
    }
}

// combined qk + qkp: grid (18, 2, 32)
__global__ void __launch_bounds__(128) gemm_qkqkp(
    const float* __restrict__ q, const float* __restrict__ k,
    const float* __restrict__ kproj,
    float* __restrict__ qk, float* __restrict__ qkp)
{
    int z = blockIdx.z, b = z >> 3, h = z & 7;
    const float* qa = q + (size_t)b * Ssz * Esz + h * HDsz;
    int bm = blockIdx.y * 64;
    if (blockIdx.x < 16) {
        gemm_mma_body(qa, Esz, kproj + h * HDsz, Esz, nullptr,
                      qkp + (size_t)b * Ssz * 8000 + h, 8000, 8,
                      bm, blockIdx.x * 64, Ssz, 1000, 0, HDsz, 0);
    } else {
        gemm_mma_body(qa, Esz, k + (size_t)b * Ssz * Esz + h * HDsz, Esz, nullptr,
                      qk + (size_t)z * Ssz * Ssz, Ssz, 1,
                      bm, (blockIdx.x - 16) * 64, Ssz, Ssz, 0, HDsz, 0);
    }
}

// attention value GEMM: asum[b,i,h*64+d] = Aext[b,h,i,:] . Wext[b,h,d,:]
// grid (1, 2, 32) = 64 CTAs, K = 288
__global__ void __launch_bounds__(128) gemm_attn(
    const float* __restrict__ Aext, const float* __restrict__ Wext,
    float* __restrict__ asum)
{
    int z = blockIdx.z, b = z >> 3, h = z & 7;
    gemm_mma_body(Aext + (size_t)z * Ssz * KEXT, KEXT,
                  Wext + (size_t)z * HDsz * KEXT, KEXT,
                  nullptr, asum + (size_t)b * Ssz * Esz + h * HDsz, Esz, 1,
                  blockIdx.y * 64, 0, Ssz, HDsz, 0, KEXT, 0);
}

// pack W_ext[b,h,d,:] = [vs^T | vo^T | pe_v^T | 0], grid 32, 256 threads
__global__ void __launch_bounds__(256) pack_w(
    const float* __restrict__ vs, const float* __restrict__ vo,
    const float* __restrict__ pe_v, float* __restrict__ Wext)
{
    int z = blockIdx.x, b = z >> 3, h = z & 7;
    int tid = threadIdx.x;
    __shared__ float vsh[128 * 65];
    float* wbase = Wext + (size_t)z * HDsz * KEXT;

    // vs transpose
    for (int idx = tid; idx < 128 * 64; idx += 256) {
        int j = idx >> 6, d = idx & 63;
        vsh[j * 65 + d] = vs[(size_t)(b * Ssz + j) * Esz + h * HDsz + d];
    }
    __syncthreads();
    {
        int w = tid >> 5, l = tid & 31;
        #pragma unroll
        for (int r = 0; r < 8; r++) {
            int d = w * 8 + r;
            float* dst = wbase + (size_t)d * KEXT;
            #pragma unroll
            for (int t = 0; t < 4; t++) {
                int j = l + 32 * t;
                dst[j] = vsh[j * 65 + d];
            }
        }
    }
    __syncthreads();
    // vo transpose
    for (int idx = tid; idx < 128 * 64; idx += 256) {
        int j = idx >> 6, d = idx & 63;
        vsh[j * 65 + d] = vo[(size_t)(b * Ssz + j) * Esz + h * HDsz + d];
    }
    __syncthreads();
    {
        int w = tid >> 5, l = tid & 31;
        #pragma unroll
        for (int r = 0; r < 8; r++) {
            int d = w * 8 + r;
            float* dst = wbase + (size_t)d * KEXT + 128;
            #pragma unroll
            for (int t = 0; t < 4; t++) {
                int j = l + 32 * t;
                dst[j] = vsh[j * 65 + d];
            }
        }
    }
    // pe_v columns + zero pad (cols 256..287)
    for (int idx = tid; idx < 64 * 32; idx += 256) {
        int d = idx >> 5, c = idx & 31;
        float v = (c < 11) ? pe_v[c * HDsz + d] : 0.f;
        wbase[(size_t)d * KEXT + 256 + c] = v;
    }
}

// ======== scores: gather + softmax + packed A_ext output ====================
__global__ void scores_kernel(const float* __restrict__ qk, const float* __restrict__ qkp,
                              const float* __restrict__ q,
                              const int* __restrict__ know_adj,
                              const int* __restrict__ pos_mask,
                              const int* __restrict__ adj,
                              const int* __restrict__ smk, const int* __restrict__ omk,
                              const float* __restrict__ pe_k,
                              float* __restrict__ Aext)
{
    int i = blockIdx.x, b = blockIdx.y;
    int tid = threadIdx.x;                  // 0..255
    __shared__ float q_sh[512];
    __shared__ float qk_sh[8 * 128];
    __shared__ float qkp_sh[128 * 9];
    __shared__ float qr[8 * 11];
    __shared__ int   ka_sh[128];
    __shared__ int   p_sh[128];

    q_sh[tid]       = q[(size_t)(b * Ssz + i) * Esz + tid];
    q_sh[tid + 256] = q[(size_t)(b * Ssz + i) * Esz + tid + 256];
    if (tid < 128) {
        int ka = know_adj[(size_t)(b * Ssz + i) * Ssz + tid];
        ka_sh[tid] = min(max(ka, 0), 999);
        int p = pos_mask[i * Ssz + tid];
        p_sh[tid] = min(max(p, 0), 10);
    }
    {
        int h = tid >> 5, j4 = (tid & 31) * 4;
        float4 v = *(const float4*)(qk + ((size_t)(b * Hn + h) * Ssz + i) * Ssz + j4);
        *(float4*)(qk_sh + h * 128 + j4) = v;
    }
    // zero A_ext pad columns (267..287) for all 8 heads
    if (tid < 168) {
        int h = tid / 21, c = tid % 21;
        Aext[((size_t)(b * Hn + h) * Ssz + i) * KEXT + 267 + c] = 0.f;
    }
    __syncthreads();

    {
        int j = tid >> 1, half = tid & 1;
        float4 g = *(const float4*)(qkp + (size_t)(b * Ssz + i) * 8000
                                    + ka_sh[j] * 8 + half * 4);
        float* dst = qkp_sh + j * 9 + half * 4;
        dst[0] = g.x; dst[1] = g.y; dst[2] = g.z; dst[3] = g.w;
    }
    if (tid < 88) {
        int h = tid / 11, p = tid % 11;
        float s = 0.f;
        const float4* pk = (const float4*)(pe_k + p * HDsz);
        const float4* qv = (const float4*)(q_sh + h * 64);
        #pragma unroll
        for (int v = 0; v < 16; v++) {
            float4 e = pk[v], qq = qv[v];
            s += qq.x * e.x + qq.y * e.y + qq.z * e.z + qq.w * e.w;
        }
        qr[h * 11 + p] = s;
    }
    __syncthreads();

    {
        int w = tid >> 5, l = tid & 31;
        float s[4];
        float m = -3.4e38f;
        #pragma unroll
        for (int t = 0; t < 4; t++) {
            int j = l + 32 * t;
            float ss = (qk_sh[w * 128 + j] + qkp_sh[j * 9 + w]
                        + qr[w * 11 + p_sh[j]]) * 0.125f;
            if (adj[(size_t)(b * Ssz + i) * Ssz + j] == 0) ss -= 1e30f;
            s[t] = ss;
            m = fmaxf(m, ss);
        }
        #pragma unroll
        for (int o = 16; o; o >>= 1) m = fmaxf(m, __shfl_xor_sync(0xffffffffu, m, o));
        float sum = 0.f;
        float e[4];
        #pragma unroll
        for (int t = 0; t < 4; t++) { e[t] = __expf(s[t] - m); sum += e[t]; }
        #pragma unroll
        for (int o = 16; o; o >>= 1) sum += __shfl_xor_sync(0xffffffffu, sum, o);
        float inv = 1.f / sum;
        size_t abase = ((size_t)(b * Hn + w) * Ssz + i) * KEXT;
        #pragma unroll
        for (int t = 0; t < 4; t++) {
            int j = l + 32 * t;
            float attn = e[t] * inv;
            Aext[abase + j]       = attn * (float)smk[(size_t)(b * Ssz + i) * Ssz + j];
            Aext[abase + 128 + j] = attn * (float)omk[(size_t)(b * Ssz + i) * Ssz + j];
            qk_sh[w * 128 + j] = attn;
        }
    }
    __syncthreads();

    if (tid < 88) {   // position histogram -> A_ext cols 256..266
        int h = tid / 11, p = tid % 11;
        float s = 0.f;
        for (int j = 0; j < 128; j++)
            if (p_sh[j] == p) s += qk_sh[h * 128 + j];
        Aext[((size_t)(b * Hn + h) * Ssz + i) * KEXT + 256 + p] = s;
    }
}

// ===== fused split-K reduce + bias + residual + layernorm ===================
__global__ void ln_red_kernel(const float* __restrict__ x, const float* __restrict__ part,
                              int KS, const float* __restrict__ bias,
                              const float* __restrict__ g, const float* __restrict__ bt,
                              float* __restrict__ dst)
{
    const int MN = Msz * Esz;
    int row = blockIdx.x;
    int tid = threadIdx.x;   // 256
    __shared__ float red[8];
    size_t i0 = (size_t)row * Esz + tid;
    size_t i1 = i0 + 256;
    float v0 = x[i0], v1 = x[i1];
    for (int z = 0; z < KS; z++) {
        v0 += part[(size_t)z * MN + i0];
        v1 += part[(size_t)z * MN + i1];
    }
    if (bias) { v0 += bias[tid]; v1 += bias[tid + 256]; }
    float s = v0 + v1;
    #pragma unroll
    for (int o = 16; o; o >>= 1) s += __shfl_xor_sync(0xffffffffu, s, o);
    if ((tid & 31) == 0) red[tid >> 5] = s;
    __syncthreads();
    float mean = 0.f;
    #pragma unroll
    for (int w = 0; w < 8; w++) mean += red[w];
    mean *= (1.f / 512.f);
    __syncthreads();
    float e0 = v0 - mean, e1 = v1 - mean;
    float s2 = e0 * e0 + e1 * e1;
    #pragma unroll
    for (int o = 16; o; o >>= 1) s2 += __shfl_xor_sync(0xffffffffu, s2, o);
    if ((tid & 31) == 0) red[tid >> 5] = s2;
    __syncthreads();
    float var = 0.f;
    #pragma unroll
    for (int w = 0; w < 8; w++) var += red[w];
    var *= (1.f / 512.f);
    float rstd = rsqrtf(var + 1e-5f);
    dst[i0] = e0 * rstd * g[tid] + bt[tid];
    dst[i1] = e1 * rstd * g[tid + 256] + bt[tid + 256];
}

// ===================== host orchestration ===================================
extern "C" void kernel_launch(void* const* d_in, const int* in_sizes, int n_in,
                              void* d_out, int out_size)
{
    const float* x        = (const float*)d_in[0];
    const int*   adj      = (const int*)d_in[1];
    const int*   smk      = (const int*)d_in[2];
    const int*   omk      = (const int*)d_in[3];
    const float* knowledge= (const float*)d_in[4];
    const int*   know_adj = (const int*)d_in[5];
    const int*   pos_mask = (const int*)d_in[6];
    const float* pe_k     = (const float*)d_in[7];
    const float* pe_v     = (const float*)d_in[8];
    const float* Wq       = (const float*)d_in[9];
    const float* Wk       = (const float*)d_in[10];
    const float* Wvs      = (const float*)d_in[11];
    const float* Wvo      = (const float*)d_in[12];
    const float* Wo       = (const float*)d_in[13];
    const float* Wkn      = (const float*)d_in[14];
    const float* ln1g     = (const float*)d_in[15];
    const float* ln1b     = (const float*)d_in[16];
    const float* w1       = (const float*)d_in[17];
    const float* b1       = (const float*)d_in[18];
    const float* w2       = (const float*)d_in[19];
    const float* b2       = (const float*)d_in[20];
    const float* ln2g     = (const float*)d_in[21];
    const float* ln2b     = (const float*)d_in[22];
    float* out = (float*)d_out;

    float *h, *qkv, *kproj, *asum, *ff, *part, *qkbuf, *qkp, *Aext, *Wext;
    cudaGetSymbolAddress((void**)&h, g_h);
    cudaGetSymbolAddress((void**)&qkv, g_qkv);
    cudaGetSymbolAddress((void**)&kproj, g_kproj);
    cudaGetSymbolAddress((void**)&asum, g_attnsum);
    cudaGetSymbolAddress((void**)&ff, g_ff);
    cudaGetSymbolAddress((void**)&part, g_part);
    cudaGetSymbolAddress((void**)&qkbuf, g_qk);
    cudaGetSymbolAddress((void**)&qkp, g_qkp);
    cudaGetSymbolAddress((void**)&Aext, g_Aext);
    cudaGetSymbolAddress((void**)&Wext, g_Wext);

    const size_t EE = (size_t)Esz * Esz;
    const size_t FE = (size_t)FFsz * Esz;
    for (int l = 0; l < Lnum; l++) {
        const float* hin = (l == 0) ? x : h;
        const float* wq  = Wq  + (size_t)l * EE;
        const float* wk  = Wk  + (size_t)l * EE;
        const float* wvs = Wvs + (size_t)l * EE;
        const float* wvo = Wvo + (size_t)l * EE;
        const float* wo  = Wo  + (size_t)l * EE;
        const float* wkn = Wkn + (size_t)l * EE;

        // q,k,vs,vo projections + knowledge projection (384 CTAs)
        gemm_layer_a<<<384, 128>>>(hin, knowledge, wq, wk, wvs, wvo, wkn, qkv, kproj);
        // qk + qkp in one launch (1152 CTAs)
        gemm_qkqkp<<<dim3(18, 2, 32), 128>>>(qkv, qkv + (size_t)Msz * Esz, kproj,
                                             qkbuf, qkp);
        // pack W_ext (vs/vo transpose + pe_v)
        pack_w<<<32, 256>>>(qkv + 2 * (size_t)Msz * Esz, qkv + 3 * (size_t)Msz * Esz,
                            pe_v, Wext);
        // scores -> packed A_ext
        scores_kernel<<<dim3(Ssz, Bsz), 256>>>(
            qkbuf, qkp, qkv, know_adj, pos_mask, adj, smk, omk, pe_k, Aext);
        // attention value GEMM (64 CTAs, K=288)
        gemm_attn<<<dim3(1, 2, 32), 128>>>(Aext, Wext, asum);
        // output projection, split-K=2 (128 CTAs) + fused reduce+LN1
        gemm_tc_splitk<<<dim3(8, 8, 2), 128>>>(asum, wo, part, Msz, Esz, Esz, 2);
        ln_red_kernel<<<Msz, 256>>>(hin, part, 2, nullptr,
                                    ln1g + l * Esz, ln1b + l * Esz, h);
        // FFN1 (256 CTAs, fused bias+relu)
        gemm_tc<<<dim3(32, 8), 128>>>(h, w1 + (size_t)l * FE, b1 + (size_t)l * FFsz,
                                      ff, Msz, FFsz, Esz, 1);
        // FFN2, split-K=4 (256 CTAs) + fused reduce+bias+LN2
        gemm_tc_splitk<<<dim3(8, 8, 4), 128>>>(ff, w2 + (size_t)l * FE, part,
                                               Msz, Esz, FFsz, 4);
        float* dst = (l == Lnum - 1) ? out : h;
        ln_red_kernel<<<Msz, 256>>>(h, part, 4, b2 + l * Esz,
                                    ln2g + l * Esz, ln2b + l * Esz, dst);
    }
}